// round 1
// baseline (speedup 1.0000x reference)
#include <cuda_runtime.h>
#include <math.h>
#include <math_constants.h>

// Problem constants
#define VOCABN 100000
#define EMBED  100
#define NOISEN 10
#define CIN    110          // EMBED + NOISE
#define HID    128
#define BATCH  2048

// GEMM tiling
#define BM 64
#define BN 64
#define NCH ((VOCABN + BN - 1) / BN)   // 1563 vocab chunks

// LSTM kernel tiling
#define A_ROWS 16
#define WPAD   111          // 110 padded to 111 (stride%32==15, conflict-free)

// Scratch (static __device__ — no allocations allowed)
__device__ float g_h[BATCH * HID];
__device__ float g_pmax[(size_t)BATCH * NCH];
__device__ float g_psum[(size_t)BATCH * NCH];
__device__ float g_M[BATCH];
__device__ float g_invZ[BATCH];

__device__ __forceinline__ float sigm(float v) { return 1.0f / (1.0f + expf(-v)); }

// ---------------------------------------------------------------------------
// Kernel A: embedding + noise concat + LSTM step -> h [2048, 128]
// Grid: 128 blocks x 256 threads, 16 batch rows per block.
// W_ih rows needed (i, g, o; f is dead since c0=0) staged in dynamic smem.
// ---------------------------------------------------------------------------
__global__ void lstm_kernel(const int* __restrict__ x,
                            const float* __restrict__ noise,
                            const float* __restrict__ emb,
                            const float* __restrict__ W_ih,
                            const float* __restrict__ b_ih,
                            const float* __restrict__ b_hh) {
    extern __shared__ float sm[];
    float* Wsm = sm;                       // [384][WPAD]
    float* Csm = sm + 384 * WPAD;          // [A_ROWS][CIN]

    const int t = threadIdx.x;             // 256 threads
    const int row0 = blockIdx.x * A_ROWS;

    // Stage W_ih rows: i -> [0,128), g -> [128,256), o -> [256,384)
    for (int idx = t; idx < 384 * CIN; idx += 256) {
        int r = idx / CIN;
        int k = idx - r * CIN;
        int gr = (r < 128) ? r : (r + 128);   // skip f block (rows 128..255)
        Wsm[r * WPAD + k] = W_ih[gr * CIN + k];
    }
    // Stage combined inputs [A_ROWS][CIN]
    for (int idx = t; idx < A_ROWS * CIN; idx += 256) {
        int r = idx / CIN;
        int k = idx - r * CIN;
        int brow = row0 + r;
        float v = (k < EMBED) ? emb[(size_t)x[brow] * EMBED + k]
                              : noise[brow * NOISEN + (k - EMBED)];
        Csm[r * CIN + k] = v;
    }
    __syncthreads();

    const int j = t & 127;        // hidden index
    const int rhalf = t >> 7;     // 0..1
    const float bi = b_ih[j]       + b_hh[j];
    const float bg = b_ih[256 + j] + b_hh[256 + j];
    const float bo = b_ih[384 + j] + b_hh[384 + j];

    const float* wi = &Wsm[j * WPAD];
    const float* wg = &Wsm[(128 + j) * WPAD];
    const float* wo = &Wsm[(256 + j) * WPAD];

    for (int rr = 0; rr < A_ROWS / 2; rr++) {
        int r = rhalf * (A_ROWS / 2) + rr;
        const float* c = &Csm[r * CIN];
        float ai = bi, ag = bg, ao = bo;
        #pragma unroll 2
        for (int k = 0; k < CIN; k++) {
            float cv = c[k];
            ai = fmaf(wi[k], cv, ai);
            ag = fmaf(wg[k], cv, ag);
            ao = fmaf(wo[k], cv, ao);
        }
        float cc = sigm(ai) * tanhf(ag);     // c0 == 0 -> f gate irrelevant
        float h  = sigm(ao) * tanhf(cc);
        g_h[(row0 + r) * HID + j] = h;
    }
}

// ---------------------------------------------------------------------------
// Kernel B: logits = h @ fc_w^T + fc_b, write logits to out, and emit
// per-(row, vocab-chunk) softmax partials (max, sumexp).
// Grid: (NCH, BATCH/BM), block 256 threads, 64x64 tile, 4x4 reg tile.
// ---------------------------------------------------------------------------
__global__ void gemm_kernel(const float* __restrict__ fc_w,
                            const float* __restrict__ fc_b,
                            float* __restrict__ out) {
    extern __shared__ float sm[];
    float* Hs   = sm;                       // [64][129]
    float* Ws   = Hs + 64 * 129;            // [64][129]
    float* red  = Ws + 64 * 129;            // [64][16]
    float* rmax = red + 64 * 16;            // [64]

    const int t = threadIdx.x;
    const int vb = blockIdx.x;
    const int mb = blockIdx.y;
    const int v0 = vb * BN;
    const int m0 = mb * BM;

    // Load Hs (64 rows x 128 k) from g_h, padded stride 129
    for (int idx = t; idx < 64 * 128; idx += 256) {
        int r = idx >> 7;
        int k = idx & 127;
        Hs[r * 129 + k] = g_h[(m0 + r) * HID + k];
    }
    // Load Ws (64 vocab rows x 128 k) from fc_w (vectorized read, scalar smem store)
    #pragma unroll
    for (int q = 0; q < 8; q++) {
        int idx = t + 256 * q;          // float4 index within tile
        int r  = idx >> 5;              // 32 float4 per row
        int k4 = idx & 31;
        int gv = v0 + r;
        float4 w = (gv < VOCABN) ? reinterpret_cast<const float4*>(fc_w)[(size_t)gv * 32 + k4]
                                 : make_float4(0.f, 0.f, 0.f, 0.f);
        float* d = &Ws[r * 129 + k4 * 4];
        d[0] = w.x; d[1] = w.y; d[2] = w.z; d[3] = w.w;
    }
    __syncthreads();

    const int tx = t & 15;
    const int ty = t >> 4;

    float acc[4][4];
    #pragma unroll
    for (int i = 0; i < 4; i++)
        #pragma unroll
        for (int jj = 0; jj < 4; jj++) acc[i][jj] = 0.f;

    #pragma unroll 4
    for (int k = 0; k < 128; k++) {
        float a[4], b[4];
        #pragma unroll
        for (int i = 0; i < 4; i++)  a[i] = Hs[(ty + 16 * i) * 129 + k];
        #pragma unroll
        for (int jj = 0; jj < 4; jj++) b[jj] = Ws[(tx + 16 * jj) * 129 + k];
        #pragma unroll
        for (int i = 0; i < 4; i++)
            #pragma unroll
            for (int jj = 0; jj < 4; jj++)
                acc[i][jj] = fmaf(a[i], b[jj], acc[i][jj]);
    }

    // Epilogue: add bias, write logits, compute tile-local softmax partials
    float vals[4][4];
    float lmax[4];
    #pragma unroll
    for (int i = 0; i < 4; i++) {
        lmax[i] = -CUDART_INF_F;
        #pragma unroll
        for (int jj = 0; jj < 4; jj++) {
            int col = v0 + tx + 16 * jj;
            float v = (col < VOCABN) ? acc[i][jj] + fc_b[col] : -CUDART_INF_F;
            vals[i][jj] = v;
            lmax[i] = fmaxf(lmax[i], v);
        }
    }
    #pragma unroll
    for (int i = 0; i < 4; i++) {
        int row = m0 + ty + 16 * i;
        #pragma unroll
        for (int jj = 0; jj < 4; jj++) {
            int col = v0 + tx + 16 * jj;
            if (col < VOCABN) out[(size_t)row * VOCABN + col] = vals[i][jj];
        }
    }

    // Tile row max over 16 tx-threads
    #pragma unroll
    for (int i = 0; i < 4; i++) red[(ty + 16 * i) * 16 + tx] = lmax[i];
    __syncthreads();
    if (t < 64) {
        float m = red[t * 16];
        #pragma unroll
        for (int q = 1; q < 16; q++) m = fmaxf(m, red[t * 16 + q]);
        rmax[t] = m;
    }
    __syncthreads();

    // Tile row sumexp (relative to tile max); exp(-inf - m) == 0 handles padding
    #pragma unroll
    for (int i = 0; i < 4; i++) {
        int rloc = ty + 16 * i;
        float m = rmax[rloc];
        float s = 0.f;
        #pragma unroll
        for (int jj = 0; jj < 4; jj++) s += expf(vals[i][jj] - m);
        red[rloc * 16 + tx] = s;
    }
    __syncthreads();
    if (t < 64) {
        float s = 0.f;
        #pragma unroll
        for (int q = 0; q < 16; q++) s += red[t * 16 + q];
        size_t o = (size_t)(m0 + t) * NCH + vb;
        g_pmax[o] = rmax[t];
        g_psum[o] = s;
    }
}

// ---------------------------------------------------------------------------
// Kernel C: per-row log-sum-exp merge of NCH partials -> M, 1/Z
// ---------------------------------------------------------------------------
__global__ void reduce_kernel() {
    const int row = blockIdx.x;
    const int t = threadIdx.x;    // 128
    float m = -CUDART_INF_F, s = 0.f;
    for (int p = t; p < NCH; p += 128) {
        float mp = g_pmax[(size_t)row * NCH + p];
        float sp = g_psum[(size_t)row * NCH + p];
        if (mp > m) { s = s * expf(m - mp) + sp; m = mp; }
        else        { s += sp * expf(mp - m); }
    }
    __shared__ float sm[128], ss[128];
    sm[t] = m; ss[t] = s;
    __syncthreads();
    for (int stride = 64; stride > 0; stride >>= 1) {
        if (t < stride) {
            float m1 = sm[t], s1 = ss[t];
            float m2 = sm[t + stride], s2 = ss[t + stride];
            float M = fmaxf(m1, m2);
            ss[t] = s1 * expf(m1 - M) + s2 * expf(m2 - M);
            sm[t] = M;
        }
        __syncthreads();
    }
    if (t == 0) { g_M[row] = sm[0]; g_invZ[row] = 1.f / ss[0]; }
}

// ---------------------------------------------------------------------------
// Kernel D: in-place normalize: out = exp(logit - M) / Z   (float4)
// ---------------------------------------------------------------------------
__global__ void softmax_kernel(float* __restrict__ out) {
    unsigned int idx = blockIdx.x * blockDim.x + threadIdx.x;  // float4 index
    const unsigned int per_row = VOCABN / 4;                    // 25000
    unsigned int row = idx / per_row;
    float m = g_M[row];
    float z = g_invZ[row];
    float4 v = reinterpret_cast<float4*>(out)[idx];
    v.x = expf(v.x - m) * z;
    v.y = expf(v.y - m) * z;
    v.z = expf(v.z - m) * z;
    v.w = expf(v.w - m) * z;
    reinterpret_cast<float4*>(out)[idx] = v;
}

// ---------------------------------------------------------------------------
extern "C" void kernel_launch(void* const* d_in, const int* in_sizes, int n_in,
                              void* d_out, int out_size) {
    const int*   x     = (const int*)d_in[0];
    const float* noise = (const float*)d_in[1];
    const float* emb   = (const float*)d_in[2];
    const float* W_ih  = (const float*)d_in[3];
    /* d_in[4] = W_hh — dead code: h0 == 0 */
    const float* b_ih  = (const float*)d_in[5];
    const float* b_hh  = (const float*)d_in[6];
    const float* fc_w  = (const float*)d_in[7];
    const float* fc_b  = (const float*)d_in[8];
    float* out = (float*)d_out;

    const int smemA = (384 * WPAD + A_ROWS * CIN) * 4;            // ~177.5 KB
    const int smemB = (64 * 129 * 2 + 64 * 16 + 64) * 4;          // ~70.4 KB
    cudaFuncSetAttribute(lstm_kernel, cudaFuncAttributeMaxDynamicSharedMemorySize, smemA);
    cudaFuncSetAttribute(gemm_kernel, cudaFuncAttributeMaxDynamicSharedMemorySize, smemB);

    lstm_kernel<<<BATCH / A_ROWS, 256, smemA>>>(x, noise, emb, W_ih, b_ih, b_hh);
    gemm_kernel<<<dim3(NCH, BATCH / BM), 256, smemB>>>(fc_w, fc_b, out);
    reduce_kernel<<<BATCH, 128>>>();
    softmax_kernel<<<(BATCH * (VOCABN / 4)) / 256, 256>>>(out);
}

// round 3
// speedup vs baseline: 2.0321x; 2.0321x over previous
#include <cuda_runtime.h>
#include <cuda_bf16.h>
#include <math.h>
#include <math_constants.h>
#include <cstdint>

// Problem constants
#define VOCABN 100000
#define EMBED  100
#define NOISEN 10
#define CIN    110
#define HID    128
#define BATCH  2048

// GEMM tiling
#define NCH 782                 // ceil(100000/128): vocab tiles of 128
#define MT16 16                 // 128-row A tiles
#define CM 256                  // CTA M super-tile
#define MITER (BATCH / CM)      // 8
#define TILE_BYTES 32768        // 128x128 bf16 tile

// LSTM kernel tiling
#define A_ROWS 16
#define WPAD   111

// ---------------------------------------------------------------------------
// Scratch (static __device__, no allocations)
// ---------------------------------------------------------------------------
__device__ __align__(16) char g_Bhi[(size_t)NCH * TILE_BYTES];   // 25.6 MB
__device__ __align__(16) char g_Blo[(size_t)NCH * TILE_BYTES];   // 25.6 MB
__device__ __align__(16) char g_Ahi[MT16 * TILE_BYTES];          // 512 KB
__device__ __align__(16) char g_Alo[MT16 * TILE_BYTES];          // 512 KB
__device__ float g_h[BATCH * HID];
__device__ float g_pmax[(size_t)BATCH * NCH];
__device__ float g_psum[(size_t)BATCH * NCH];
__device__ float g_M[BATCH];
__device__ float g_invZ[BATCH];

__device__ __forceinline__ float sigm(float v) { return 1.0f / (1.0f + expf(-v)); }

__device__ __forceinline__ uint32_t smem_to_u32(const void* p) {
    uint32_t a;
    asm("{ .reg .u64 t; cvta.to.shared.u64 t, %1; cvt.u32.u64 %0, t; }" : "=r"(a) : "l"(p));
    return a;
}

// Blocked-atom SW128 byte offset inside a 128x128 bf16 tile.
// atom = 8 rows x 64 bf16 (1024B); 16 atom-rows x 2 atom-cols; swizzle XORs
// the 16B-chunk index with inner_row (bits [6:4] ^= inner_row).
__host__ __device__ __forceinline__ uint32_t tile_off(int row, int col) {
    return (uint32_t)(((((row & 127) >> 3) + ((col >> 6) << 4)) << 10) + ((row >> 7) << 15) +
                      ((row & 7) << 7) + ((((col & 63) << 1)) ^ ((row & 7) << 4)));
}

// ldmatrix x4 (non-transposed, b16)
__device__ __forceinline__ void ldsm_x4(uint32_t* r, uint32_t addr) {
    asm volatile("ldmatrix.sync.aligned.m8n8.x4.shared.b16 {%0,%1,%2,%3}, [%4];"
                 : "=r"(r[0]), "=r"(r[1]), "=r"(r[2]), "=r"(r[3]) : "r"(addr));
}

// Load one 16x16 bf16 block as 4 8x8 matrices (rows = leading dim of the tile).
// Lane i supplies row of matrix i>>3: m0=[r0..7,c0..7] m1=[r8..15,c0..7]
// m2=[r0..7,c8..15] m3=[r8..15,c8..15]
__device__ __forceinline__ void ldsm_block(uint32_t* r, uint32_t base, int row0, int col0, int lane) {
    int sub = lane >> 3, rr = lane & 7;
    int row = row0 + ((sub & 1) << 3) + rr;
    int col = col0 + ((sub >> 1) << 3);
    ldsm_x4(r, base + tile_off(row, col));
}

// mma.m16n8k16 row.col bf16 -> fp32 accumulate
__device__ __forceinline__ void mma16816(float* c, const uint32_t* a, uint32_t b0, uint32_t b1) {
    asm volatile(
        "mma.sync.aligned.m16n8k16.row.col.f32.bf16.bf16.f32 "
        "{%0,%1,%2,%3}, {%4,%5,%6,%7}, {%8,%9}, {%0,%1,%2,%3};"
        : "+f"(c[0]), "+f"(c[1]), "+f"(c[2]), "+f"(c[3])
        : "r"(a[0]), "r"(a[1]), "r"(a[2]), "r"(a[3]), "r"(b0), "r"(b1));
}

// ---------------------------------------------------------------------------
// Kernel A: embedding + noise + LSTM step -> g_h [2048, 128] fp32
// ---------------------------------------------------------------------------
__global__ void lstm_kernel(const int* __restrict__ x,
                            const float* __restrict__ noise,
                            const float* __restrict__ emb,
                            const float* __restrict__ W_ih,
                            const float* __restrict__ b_ih,
                            const float* __restrict__ b_hh) {
    extern __shared__ float sm[];
    float* Wsm = sm;                       // [384][WPAD]
    float* Csm = sm + 384 * WPAD;          // [A_ROWS][CIN]

    const int t = threadIdx.x;
    const int row0 = blockIdx.x * A_ROWS;

    for (int idx = t; idx < 384 * CIN; idx += 256) {
        int r = idx / CIN;
        int k = idx - r * CIN;
        int gr = (r < 128) ? r : (r + 128);   // skip dead f block
        Wsm[r * WPAD + k] = W_ih[gr * CIN + k];
    }
    for (int idx = t; idx < A_ROWS * CIN; idx += 256) {
        int r = idx / CIN;
        int k = idx - r * CIN;
        int brow = row0 + r;
        float v = (k < EMBED) ? emb[(size_t)x[brow] * EMBED + k]
                              : noise[brow * NOISEN + (k - EMBED)];
        Csm[r * CIN + k] = v;
    }
    __syncthreads();

    const int j = t & 127;
    const int rhalf = t >> 7;
    const float bi = b_ih[j]       + b_hh[j];
    const float bg = b_ih[256 + j] + b_hh[256 + j];
    const float bo = b_ih[384 + j] + b_hh[384 + j];

    const float* wi = &Wsm[j * WPAD];
    const float* wg = &Wsm[(128 + j) * WPAD];
    const float* wo = &Wsm[(256 + j) * WPAD];

    for (int rr = 0; rr < A_ROWS / 2; rr++) {
        int r = rhalf * (A_ROWS / 2) + rr;
        const float* c = &Csm[r * CIN];
        float ai = bi, ag = bg, ao = bo;
        #pragma unroll 2
        for (int k = 0; k < CIN; k++) {
            float cv = c[k];
            ai = fmaf(wi[k], cv, ai);
            ag = fmaf(wg[k], cv, ag);
            ao = fmaf(wo[k], cv, ao);
        }
        float cc = sigm(ai) * tanhf(ag);
        float h  = sigm(ao) * tanhf(cc);
        g_h[(row0 + r) * HID + j] = h;
    }
}

// ---------------------------------------------------------------------------
// Convert fc_w -> swizzled bf16 hi/lo tiles (pad rows beyond VOCAB with 0)
// ---------------------------------------------------------------------------
__global__ void convert_w_kernel(const float* __restrict__ fc_w) {
    int c = blockIdx.x * blockDim.x + threadIdx.x;     // 16B-chunk id
    int tile = c >> 11;
    int q = c & 2047;
    int row = q >> 4;
    int kc = q & 15;
    int v = tile * 128 + row;

    float4 w0, w1;
    if (v < VOCABN) {
        const float4* src = reinterpret_cast<const float4*>(fc_w + (size_t)v * HID + kc * 8);
        w0 = src[0]; w1 = src[1];
    } else {
        w0 = w1 = make_float4(0.f, 0.f, 0.f, 0.f);
    }
    float f[8] = {w0.x, w0.y, w0.z, w0.w, w1.x, w1.y, w1.z, w1.w};
    __nv_bfloat16 hi[8], lo[8];
    #pragma unroll
    for (int i = 0; i < 8; i++) {
        hi[i] = __float2bfloat16(f[i]);
        lo[i] = __float2bfloat16(f[i] - __bfloat162float(hi[i]));
    }
    size_t off = (size_t)tile * TILE_BYTES + tile_off(row, kc * 8);
    *reinterpret_cast<uint4*>(g_Bhi + off) = *reinterpret_cast<uint4*>(hi);
    *reinterpret_cast<uint4*>(g_Blo + off) = *reinterpret_cast<uint4*>(lo);
}

// ---------------------------------------------------------------------------
// Convert g_h -> swizzled bf16 hi/lo A tiles
// ---------------------------------------------------------------------------
__global__ void convert_a_kernel() {
    int c = blockIdx.x * blockDim.x + threadIdx.x;     // 16B-chunk id, 32768 total
    int tile = c >> 11;
    int q = c & 2047;
    int row = q >> 4;
    int kc = q & 15;
    const float4* src = reinterpret_cast<const float4*>(g_h + (size_t)(tile * 128 + row) * HID + kc * 8);
    float4 w0 = src[0], w1 = src[1];
    float f[8] = {w0.x, w0.y, w0.z, w0.w, w1.x, w1.y, w1.z, w1.w};
    __nv_bfloat16 hi[8], lo[8];
    #pragma unroll
    for (int i = 0; i < 8; i++) {
        hi[i] = __float2bfloat16(f[i]);
        lo[i] = __float2bfloat16(f[i] - __bfloat162float(hi[i]));
    }
    size_t off = (size_t)tile * TILE_BYTES + tile_off(row, kc * 8);
    *reinterpret_cast<uint4*>(g_Ahi + off) = *reinterpret_cast<uint4*>(hi);
    *reinterpret_cast<uint4*>(g_Alo + off) = *reinterpret_cast<uint4*>(lo);
}

// ---------------------------------------------------------------------------
// Tensor-core GEMM (mma.sync bf16 hi/lo, 3 passes) + fused softmax partials.
// CTA: one vocab tile (N=128), loops 8 M super-tiles of 256 rows.
// 8 warps = 4(M) x 2(N); warp tile 64x64.
// ---------------------------------------------------------------------------
#define OFF_BHI   0
#define OFF_BLO   32768
#define OFF_AHI   65536          // 64 KB: two 128-row tiles
#define OFF_ALO   131072         // 64 KB
#define OFF_BIAS  196608         // 512 B
#define OFF_REDM  197120         // 256*2 fp32 = 2 KB
#define OFF_REDS  199168         // 2 KB
#define SMEM_GEMM 201216

__global__ __launch_bounds__(256, 1) void gemm_tc(const float* __restrict__ fc_b,
                                                  float* __restrict__ out) {
    extern __shared__ char smem[];
    const int t = threadIdx.x, wid = t >> 5, lane = t & 31;
    const int vb = blockIdx.x;
    const uint32_t sb = smem_to_u32(smem);

    const int wm = wid >> 1;      // 0..3 : M warp row (64 rows each)
    const int wn = wid & 1;       // 0..1 : N warp col (64 cols each)
    const int g = lane >> 2, t4 = lane & 3;

    // Stage B hi/lo tiles + bias (resident for whole kernel)
    {
        const uint4* gh = reinterpret_cast<const uint4*>(g_Bhi + (size_t)vb * TILE_BYTES);
        const uint4* gl = reinterpret_cast<const uint4*>(g_Blo + (size_t)vb * TILE_BYTES);
        uint4* sh = reinterpret_cast<uint4*>(smem + OFF_BHI);
        uint4* sl = reinterpret_cast<uint4*>(smem + OFF_BLO);
        #pragma unroll
        for (int i = 0; i < 8; i++) {
            sh[t + 256 * i] = gh[t + 256 * i];
            sl[t + 256 * i] = gl[t + 256 * i];
        }
    }
    if (t < 128) {
        int gc = vb * 128 + t;
        reinterpret_cast<float*>(smem + OFF_BIAS)[t] = (gc < VOCABN) ? fc_b[gc] : -CUDART_INF_F;
    }

    const uint32_t sBhi = sb + OFF_BHI, sBlo = sb + OFF_BLO;
    const uint32_t sAhi = sb + OFF_AHI, sAlo = sb + OFF_ALO;
    float* bias = reinterpret_cast<float*>(smem + OFF_BIAS);
    float* redm = reinterpret_cast<float*>(smem + OFF_REDM);
    float* reds = reinterpret_cast<float*>(smem + OFF_REDS);

    for (int mt = 0; mt < MITER; mt++) {
        // Load A super-tile (two 128-tiles, hi+lo = 128 KB)
        {
            const uint4* gh = reinterpret_cast<const uint4*>(g_Ahi + (size_t)(mt * 2) * TILE_BYTES);
            const uint4* gl = reinterpret_cast<const uint4*>(g_Alo + (size_t)(mt * 2) * TILE_BYTES);
            uint4* sh = reinterpret_cast<uint4*>(smem + OFF_AHI);
            uint4* sl = reinterpret_cast<uint4*>(smem + OFF_ALO);
            #pragma unroll
            for (int i = 0; i < 16; i++) {
                sh[t + 256 * i] = gh[t + 256 * i];
                sl[t + 256 * i] = gl[t + 256 * i];
            }
        }
        __syncthreads();

        float acc[4][8][4];
        #pragma unroll
        for (int mb = 0; mb < 4; mb++)
            #pragma unroll
            for (int nb = 0; nb < 8; nb++)
                #pragma unroll
                for (int r = 0; r < 4; r++) acc[mb][nb][r] = 0.f;

        const int am0 = wm * 64;
        const int bn0 = wn * 64;

        #pragma unroll
        for (int ks = 0; ks < 8; ks++) {
            const int k0 = ks * 16;
            uint32_t ah[4][4], bh[4][4], bx[4][4];

            #pragma unroll
            for (int mb = 0; mb < 4; mb++) ldsm_block(ah[mb], sAhi, am0 + mb * 16, k0, lane);
            #pragma unroll
            for (int nbb = 0; nbb < 4; nbb++) ldsm_block(bh[nbb], sBhi, bn0 + nbb * 16, k0, lane);

            // pass 1: hi*hi
            #pragma unroll
            for (int mb = 0; mb < 4; mb++)
                #pragma unroll
                for (int nbb = 0; nbb < 4; nbb++) {
                    mma16816(acc[mb][2 * nbb],     ah[mb], bh[nbb][0], bh[nbb][2]);
                    mma16816(acc[mb][2 * nbb + 1], ah[mb], bh[nbb][1], bh[nbb][3]);
                }
            // pass 2: hi*lo
            #pragma unroll
            for (int nbb = 0; nbb < 4; nbb++) ldsm_block(bx[nbb], sBlo, bn0 + nbb * 16, k0, lane);
            #pragma unroll
            for (int mb = 0; mb < 4; mb++)
                #pragma unroll
                for (int nbb = 0; nbb < 4; nbb++) {
                    mma16816(acc[mb][2 * nbb],     ah[mb], bx[nbb][0], bx[nbb][2]);
                    mma16816(acc[mb][2 * nbb + 1], ah[mb], bx[nbb][1], bx[nbb][3]);
                }
            // pass 3: lo*hi (reuse ah regs for A-lo)
            #pragma unroll
            for (int mb = 0; mb < 4; mb++) ldsm_block(bx[mb], sAlo, am0 + mb * 16, k0, lane);
            #pragma unroll
            for (int mb = 0; mb < 4; mb++)
                #pragma unroll
                for (int nbb = 0; nbb < 4; nbb++) {
                    mma16816(acc[mb][2 * nbb],     bx[mb], bh[nbb][0], bh[nbb][2]);
                    mma16816(acc[mb][2 * nbb + 1], bx[mb], bh[nbb][1], bh[nbb][3]);
                }
        }

        // ---- Epilogue: bias add, logits STG, softmax partials ----
        const int mbase = mt * CM;
        #pragma unroll
        for (int mb = 0; mb < 4; mb++) {
            #pragma unroll
            for (int h = 0; h < 2; h++) {
                int rl = wm * 64 + mb * 16 + h * 8 + g;     // local row
                float mx = -CUDART_INF_F;
                #pragma unroll
                for (int nb = 0; nb < 8; nb++) {
                    int cl = wn * 64 + nb * 8 + t4 * 2;
                    float v0 = acc[mb][nb][h * 2]     + bias[cl];
                    float v1 = acc[mb][nb][h * 2 + 1] + bias[cl + 1];
                    acc[mb][nb][h * 2] = v0;
                    acc[mb][nb][h * 2 + 1] = v1;
                    mx = fmaxf(mx, fmaxf(v0, v1));
                }
                mx = fmaxf(mx, __shfl_xor_sync(0xffffffffu, mx, 1));
                mx = fmaxf(mx, __shfl_xor_sync(0xffffffffu, mx, 2));
                if (t4 == 0) redm[rl * 2 + wn] = mx;
                // write logits
                size_t rb = (size_t)(mbase + rl) * VOCABN;
                #pragma unroll
                for (int nb = 0; nb < 8; nb++) {
                    int gcol = vb * 128 + wn * 64 + nb * 8 + t4 * 2;
                    if (gcol < VOCABN) {
                        float2 w = make_float2(acc[mb][nb][h * 2], acc[mb][nb][h * 2 + 1]);
                        *reinterpret_cast<float2*>(out + rb + gcol) = w;
                    }
                }
            }
        }
        __syncthreads();
        #pragma unroll
        for (int mb = 0; mb < 4; mb++) {
            #pragma unroll
            for (int h = 0; h < 2; h++) {
                int rl = wm * 64 + mb * 16 + h * 8 + g;
                float gm = fmaxf(redm[rl * 2], redm[rl * 2 + 1]);
                float s = 0.f;
                #pragma unroll
                for (int nb = 0; nb < 8; nb++)
                    s += expf(acc[mb][nb][h * 2] - gm) + expf(acc[mb][nb][h * 2 + 1] - gm);
                s += __shfl_xor_sync(0xffffffffu, s, 1);
                s += __shfl_xor_sync(0xffffffffu, s, 2);
                if (t4 == 0) reds[rl * 2 + wn] = s;
            }
        }
        __syncthreads();
        if (t < CM) {
            g_pmax[(size_t)(mbase + t) * NCH + vb] = fmaxf(redm[t * 2], redm[t * 2 + 1]);
            g_psum[(size_t)(mbase + t) * NCH + vb] = reds[t * 2] + reds[t * 2 + 1];
        }
        __syncthreads();
    }
}

// ---------------------------------------------------------------------------
// Kernel C: per-row log-sum-exp merge of NCH partials -> M, 1/Z
// ---------------------------------------------------------------------------
__global__ void reduce_kernel() {
    const int row = blockIdx.x;
    const int t = threadIdx.x;    // 128
    float m = -CUDART_INF_F, s = 0.f;
    for (int p = t; p < NCH; p += 128) {
        float mp = g_pmax[(size_t)row * NCH + p];
        float sp = g_psum[(size_t)row * NCH + p];
        if (mp > m) { s = s * expf(m - mp) + sp; m = mp; }
        else        { s += sp * expf(mp - m); }
    }
    __shared__ float sm[128], ss[128];
    sm[t] = m; ss[t] = s;
    __syncthreads();
    for (int stride = 64; stride > 0; stride >>= 1) {
        if (t < stride) {
            float m1 = sm[t], s1 = ss[t];
            float m2 = sm[t + stride], s2 = ss[t + stride];
            float M = fmaxf(m1, m2);
            ss[t] = s1 * expf(m1 - M) + s2 * expf(m2 - M);
            sm[t] = M;
        }
        __syncthreads();
    }
    if (t == 0) { g_M[row] = sm[0]; g_invZ[row] = 1.f / ss[0]; }
}

// ---------------------------------------------------------------------------
// Kernel D: in-place normalize: out = exp(logit - M) / Z   (float4)
// ---------------------------------------------------------------------------
__global__ void softmax_kernel(float* __restrict__ out) {
    unsigned int idx = blockIdx.x * blockDim.x + threadIdx.x;
    const unsigned int per_row = VOCABN / 4;
    unsigned int row = idx / per_row;
    float m = g_M[row];
    float z = g_invZ[row];
    float4 v = reinterpret_cast<float4*>(out)[idx];
    v.x = expf(v.x - m) * z;
    v.y = expf(v.y - m) * z;
    v.z = expf(v.z - m) * z;
    v.w = expf(v.w - m) * z;
    reinterpret_cast<float4*>(out)[idx] = v;
}

// ---------------------------------------------------------------------------
extern "C" void kernel_launch(void* const* d_in, const int* in_sizes, int n_in,
                              void* d_out, int out_size) {
    const int*   x     = (const int*)d_in[0];
    const float* noise = (const float*)d_in[1];
    const float* emb   = (const float*)d_in[2];
    const float* W_ih  = (const float*)d_in[3];
    /* d_in[4] = W_hh — dead: h0 == 0 */
    const float* b_ih  = (const float*)d_in[5];
    const float* b_hh  = (const float*)d_in[6];
    const float* fc_w  = (const float*)d_in[7];
    const float* fc_b  = (const float*)d_in[8];
    float* out = (float*)d_out;

    const int smemA = (384 * WPAD + A_ROWS * CIN) * 4;
    cudaFuncSetAttribute(lstm_kernel, cudaFuncAttributeMaxDynamicSharedMemorySize, smemA);
    cudaFuncSetAttribute(gemm_tc, cudaFuncAttributeMaxDynamicSharedMemorySize, SMEM_GEMM);

    convert_w_kernel<<<(NCH * 2048) / 256, 256>>>(fc_w);
    lstm_kernel<<<BATCH / A_ROWS, 256, smemA>>>(x, noise, emb, W_ih, b_ih, b_hh);
    convert_a_kernel<<<(MT16 * 2048) / 256, 256>>>();
    gemm_tc<<<NCH, 256, SMEM_GEMM>>>(fc_b, out);
    reduce_kernel<<<BATCH, 128>>>();
    softmax_kernel<<<(BATCH * (VOCABN / 4)) / 256, 256>>>(out);
}

// round 5
// speedup vs baseline: 3.2769x; 1.6126x over previous
#include <cuda_runtime.h>
#include <cuda_bf16.h>
#include <math.h>
#include <math_constants.h>
#include <cstdint>

// Problem constants
#define VOCABN 100000
#define EMBED  100
#define NOISEN 10
#define CIN    110
#define HID    128
#define BATCH  2048

// GEMM tiling
#define NCH 782                 // ceil(100000/128): vocab tiles of 128
#define MT16 16                 // 128-row A tiles
#define TILE_BYTES 32768        // 128x128 bf16 tile

// LSTM kernel tiling
#define A_ROWS 16
#define WPAD   111

// ---------------------------------------------------------------------------
// Scratch (static __device__, no allocations)
// ---------------------------------------------------------------------------
__device__ __align__(16) char g_B[(size_t)NCH * TILE_BYTES];     // 25.6 MB bf16 tiles
__device__ __align__(16) char g_A[MT16 * TILE_BYTES];            // 512 KB
__device__ float g_h[BATCH * HID];
__device__ float g_pmax[(size_t)BATCH * NCH];
__device__ float g_psum[(size_t)BATCH * NCH];
__device__ float g_M[BATCH];
__device__ float g_invZ[BATCH];

__device__ __forceinline__ float sigm(float v) { return 1.0f / (1.0f + expf(-v)); }

__device__ __forceinline__ uint32_t smem_to_u32(const void* p) {
    uint32_t a;
    asm("{ .reg .u64 t; cvta.to.shared.u64 t, %1; cvt.u32.u64 %0, t; }" : "=r"(a) : "l"(p));
    return a;
}

// Blocked-atom SW128 byte offset inside a 128x128 bf16 tile (conflict-free ldsm)
__host__ __device__ __forceinline__ uint32_t tile_off(int row, int col) {
    return (uint32_t)((((row >> 3) + ((col >> 6) << 4)) << 10) +
                      ((row & 7) << 7) + ((((col & 63) << 1)) ^ ((row & 7) << 4)));
}

__device__ __forceinline__ void ldsm_x4(uint32_t* r, uint32_t addr) {
    asm volatile("ldmatrix.sync.aligned.m8n8.x4.shared.b16 {%0,%1,%2,%3}, [%4];"
                 : "=r"(r[0]), "=r"(r[1]), "=r"(r[2]), "=r"(r[3]) : "r"(addr));
}

// Load one 16x16 bf16 block as 4 8x8 matrices.
__device__ __forceinline__ void ldsm_block(uint32_t* r, uint32_t base, int row0, int col0, int lane) {
    int sub = lane >> 3, rr = lane & 7;
    int row = row0 + ((sub & 1) << 3) + rr;
    int col = col0 + ((sub >> 1) << 3);
    ldsm_x4(r, base + tile_off(row, col));
}

// mma.m16n8k16 row.col bf16 -> fp32 accumulate
__device__ __forceinline__ void mma16816(float* c, const uint32_t* a, uint32_t b0, uint32_t b1) {
    asm volatile(
        "mma.sync.aligned.m16n8k16.row.col.f32.bf16.bf16.f32 "
        "{%0,%1,%2,%3}, {%4,%5,%6,%7}, {%8,%9}, {%0,%1,%2,%3};"
        : "+f"(c[0]), "+f"(c[1]), "+f"(c[2]), "+f"(c[3])
        : "r"(a[0]), "r"(a[1]), "r"(a[2]), "r"(a[3]), "r"(b0), "r"(b1));
}

__device__ __forceinline__ void cp_async16(uint32_t saddr, const void* gaddr) {
    asm volatile("cp.async.cg.shared.global [%0], [%1], 16;" :: "r"(saddr), "l"(gaddr));
}
#define CP_COMMIT() asm volatile("cp.async.commit_group;" ::: "memory")
#define CP_WAIT0()  asm volatile("cp.async.wait_group 0;" ::: "memory")

// ---------------------------------------------------------------------------
// Kernel A: embedding + noise + LSTM step -> g_h [2048, 128] fp32
// ---------------------------------------------------------------------------
__global__ void lstm_kernel(const int* __restrict__ x,
                            const float* __restrict__ noise,
                            const float* __restrict__ emb,
                            const float* __restrict__ W_ih,
                            const float* __restrict__ b_ih,
                            const float* __restrict__ b_hh) {
    extern __shared__ float sm[];
    float* Wsm = sm;                       // [384][WPAD]
    float* Csm = sm + 384 * WPAD;          // [A_ROWS][CIN]

    const int t = threadIdx.x;
    const int row0 = blockIdx.x * A_ROWS;

    for (int idx = t; idx < 384 * CIN; idx += 256) {
        int r = idx / CIN;
        int k = idx - r * CIN;
        int gr = (r < 128) ? r : (r + 128);   // skip dead f block
        Wsm[r * WPAD + k] = W_ih[gr * CIN + k];
    }
    for (int idx = t; idx < A_ROWS * CIN; idx += 256) {
        int r = idx / CIN;
        int k = idx - r * CIN;
        int brow = row0 + r;
        float v = (k < EMBED) ? emb[(size_t)x[brow] * EMBED + k]
                              : noise[brow * NOISEN + (k - EMBED)];
        Csm[r * CIN + k] = v;
    }
    __syncthreads();

    const int j = t & 127;
    const int rhalf = t >> 7;
    const float bi = b_ih[j]       + b_hh[j];
    const float bg = b_ih[256 + j] + b_hh[256 + j];
    const float bo = b_ih[384 + j] + b_hh[384 + j];

    const float* wi = &Wsm[j * WPAD];
    const float* wg = &Wsm[(128 + j) * WPAD];
    const float* wo = &Wsm[(256 + j) * WPAD];

    for (int rr = 0; rr < A_ROWS / 2; rr++) {
        int r = rhalf * (A_ROWS / 2) + rr;
        const float* c = &Csm[r * CIN];
        float ai = bi, ag = bg, ao = bo;
        #pragma unroll 2
        for (int k = 0; k < CIN; k++) {
            float cv = c[k];
            ai = fmaf(wi[k], cv, ai);
            ag = fmaf(wg[k], cv, ag);
            ao = fmaf(wo[k], cv, ao);
        }
        float cc = sigm(ai) * tanhf(ag);
        float h  = sigm(ao) * tanhf(cc);
        g_h[(row0 + r) * HID + j] = h;
    }
}

// ---------------------------------------------------------------------------
// Convert fc_w -> swizzled bf16 tiles (pad rows beyond VOCAB with 0)
// ---------------------------------------------------------------------------
__global__ void convert_w_kernel(const float* __restrict__ fc_w) {
    int c = blockIdx.x * blockDim.x + threadIdx.x;     // 16B-chunk id
    int tile = c >> 11;
    int q = c & 2047;
    int row = q >> 4;
    int kc = q & 15;
    int v = tile * 128 + row;

    float4 w0, w1;
    if (v < VOCABN) {
        const float4* src = reinterpret_cast<const float4*>(fc_w + (size_t)v * HID + kc * 8);
        w0 = src[0]; w1 = src[1];
    } else {
        w0 = w1 = make_float4(0.f, 0.f, 0.f, 0.f);
    }
    float f[8] = {w0.x, w0.y, w0.z, w0.w, w1.x, w1.y, w1.z, w1.w};
    __nv_bfloat16 hv[8];
    #pragma unroll
    for (int i = 0; i < 8; i++) hv[i] = __float2bfloat16(f[i]);
    size_t off = (size_t)tile * TILE_BYTES + tile_off(row, kc * 8);
    *reinterpret_cast<uint4*>(g_B + off) = *reinterpret_cast<uint4*>(hv);
}

// ---------------------------------------------------------------------------
// Convert g_h -> swizzled bf16 A tiles
// ---------------------------------------------------------------------------
__global__ void convert_a_kernel() {
    int c = blockIdx.x * blockDim.x + threadIdx.x;     // 16B-chunk id, 32768 total
    int tile = c >> 11;
    int q = c & 2047;
    int row = q >> 4;
    int kc = q & 15;
    const float4* src = reinterpret_cast<const float4*>(g_h + (size_t)(tile * 128 + row) * HID + kc * 8);
    float4 w0 = src[0], w1 = src[1];
    float f[8] = {w0.x, w0.y, w0.z, w0.w, w1.x, w1.y, w1.z, w1.w};
    __nv_bfloat16 hv[8];
    #pragma unroll
    for (int i = 0; i < 8; i++) hv[i] = __float2bfloat16(f[i]);
    size_t off = (size_t)tile * TILE_BYTES + tile_off(row, kc * 8);
    *reinterpret_cast<uint4*>(g_A + off) = *reinterpret_cast<uint4*>(hv);
}

// ---------------------------------------------------------------------------
// Tensor-core GEMM, single-pass bf16, fused bias + logits + softmax partials.
// CTA: one vocab tile (N=128), loops over 16 M tiles of 128 rows.
// 8 warps = 4(M) x 2(N); warp tile 32x64. A double-buffered via cp.async.
// 2 CTAs/SM.
// ---------------------------------------------------------------------------
#define OFF_B     0              // 32 KB
#define OFF_A     32768          // 2 x 32 KB
#define OFF_BIAS  98304          // 512 B
#define OFF_REDM  98816          // 128*2 fp32 = 1 KB
#define OFF_REDS  99840          // 1 KB
#define SMEM_GEMM 100864

__global__ __launch_bounds__(256, 2) void gemm_tc(const float* __restrict__ fc_b,
                                                  float* __restrict__ out) {
    extern __shared__ char smem[];
    const int t = threadIdx.x, wid = t >> 5, lane = t & 31;
    const int vb = blockIdx.x;
    const uint32_t sb = smem_to_u32(smem);

    const int wm = wid >> 1;      // 0..3 : 32-row slab
    const int wn = wid & 1;       // 0..1 : 64-col slab
    const int g = lane >> 2, t4 = lane & 3;

    // Stage B tile + bias; start A[0] prefetch
    {
        const uint4* gb = reinterpret_cast<const uint4*>(g_B + (size_t)vb * TILE_BYTES);
        uint4* sbp = reinterpret_cast<uint4*>(smem + OFF_B);
        #pragma unroll
        for (int i = 0; i < 8; i++) sbp[t + 256 * i] = gb[t + 256 * i];
    }
    #pragma unroll
    for (int i = 0; i < 8; i++)
        cp_async16(sb + OFF_A + t * 16 + i * 4096, g_A + t * 16 + i * 4096);
    CP_COMMIT();
    if (t < 128) {
        int gc = vb * 128 + t;
        reinterpret_cast<float*>(smem + OFF_BIAS)[t] = (gc < VOCABN) ? fc_b[gc] : -CUDART_INF_F;
    }
    CP_WAIT0();
    __syncthreads();

    const uint32_t sB = sb + OFF_B;
    float* bias = reinterpret_cast<float*>(smem + OFF_BIAS);
    float* redm = reinterpret_cast<float*>(smem + OFF_REDM);
    float* reds = reinterpret_cast<float*>(smem + OFF_REDS);

    const int am0 = wm * 32;
    const int bn0 = wn * 64;

    for (int mt = 0; mt < MT16; mt++) {
        // Prefetch next A tile into the other buffer
        if (mt + 1 < MT16) {
            uint32_t dst = sb + OFF_A + ((mt + 1) & 1) * TILE_BYTES;
            const char* src = g_A + (size_t)(mt + 1) * TILE_BYTES;
            #pragma unroll
            for (int i = 0; i < 8; i++)
                cp_async16(dst + t * 16 + i * 4096, src + t * 16 + i * 4096);
            CP_COMMIT();
        }

        const uint32_t sA = sb + OFF_A + (mt & 1) * TILE_BYTES;

        float acc[2][8][4];
        #pragma unroll
        for (int mb = 0; mb < 2; mb++)
            #pragma unroll
            for (int nb = 0; nb < 8; nb++)
                #pragma unroll
                for (int r = 0; r < 4; r++) acc[mb][nb][r] = 0.f;

        #pragma unroll
        for (int ks = 0; ks < 8; ks++) {
            const int k0 = ks * 16;
            uint32_t a[2][4], b[4][4];
            #pragma unroll
            for (int mb = 0; mb < 2; mb++) ldsm_block(a[mb], sA, am0 + mb * 16, k0, lane);
            #pragma unroll
            for (int nbb = 0; nbb < 4; nbb++) ldsm_block(b[nbb], sB, bn0 + nbb * 16, k0, lane);
            #pragma unroll
            for (int mb = 0; mb < 2; mb++)
                #pragma unroll
                for (int nbb = 0; nbb < 4; nbb++) {
                    mma16816(acc[mb][2 * nbb],     a[mb], b[nbb][0], b[nbb][2]);
                    mma16816(acc[mb][2 * nbb + 1], a[mb], b[nbb][1], b[nbb][3]);
                }
        }

        // ---- Epilogue: bias, logits STG, softmax partials ----
        const int mbase = mt * 128;
        #pragma unroll
        for (int mb = 0; mb < 2; mb++) {
            #pragma unroll
            for (int h = 0; h < 2; h++) {
                int rl = am0 + mb * 16 + h * 8 + g;
                float mx = -CUDART_INF_F;
                #pragma unroll
                for (int nb = 0; nb < 8; nb++) {
                    int cl = bn0 + nb * 8 + t4 * 2;
                    float v0 = acc[mb][nb][h * 2]     + bias[cl];
                    float v1 = acc[mb][nb][h * 2 + 1] + bias[cl + 1];
                    acc[mb][nb][h * 2] = v0;
                    acc[mb][nb][h * 2 + 1] = v1;
                    mx = fmaxf(mx, fmaxf(v0, v1));
                }
                mx = fmaxf(mx, __shfl_xor_sync(0xffffffffu, mx, 1));
                mx = fmaxf(mx, __shfl_xor_sync(0xffffffffu, mx, 2));
                if (t4 == 0) redm[rl * 2 + wn] = mx;
                size_t rb = (size_t)(mbase + rl) * VOCABN;
                #pragma unroll
                for (int nb = 0; nb < 8; nb++) {
                    int gcol = vb * 128 + bn0 + nb * 8 + t4 * 2;
                    if (gcol < VOCABN) {
                        float2 w = make_float2(acc[mb][nb][h * 2], acc[mb][nb][h * 2 + 1]);
                        *reinterpret_cast<float2*>(out + rb + gcol) = w;
                    }
                }
            }
        }
        __syncthreads();
        #pragma unroll
        for (int mb = 0; mb < 2; mb++) {
            #pragma unroll
            for (int h = 0; h < 2; h++) {
                int rl = am0 + mb * 16 + h * 8 + g;
                float gm = fmaxf(redm[rl * 2], redm[rl * 2 + 1]);
                float s = 0.f;
                #pragma unroll
                for (int nb = 0; nb < 8; nb++)
                    s += expf(acc[mb][nb][h * 2] - gm) + expf(acc[mb][nb][h * 2 + 1] - gm);
                s += __shfl_xor_sync(0xffffffffu, s, 1);
                s += __shfl_xor_sync(0xffffffffu, s, 2);
                if (t4 == 0) reds[rl * 2 + wn] = s;
            }
        }
        __syncthreads();
        if (t < 128) {
            g_pmax[(size_t)(mbase + t) * NCH + vb] = fmaxf(redm[t * 2], redm[t * 2 + 1]);
            g_psum[(size_t)(mbase + t) * NCH + vb] = reds[t * 2] + reds[t * 2 + 1];
        }
        CP_WAIT0();
        __syncthreads();
    }
}

// ---------------------------------------------------------------------------
// Kernel C: per-row log-sum-exp merge of NCH partials -> M, 1/Z
// ---------------------------------------------------------------------------
__global__ void reduce_kernel() {
    const int row = blockIdx.x;
    const int t = threadIdx.x;    // 128
    float m = -CUDART_INF_F, s = 0.f;
    for (int p = t; p < NCH; p += 128) {
        float mp = g_pmax[(size_t)row * NCH + p];
        float sp = g_psum[(size_t)row * NCH + p];
        if (mp > m) { s = s * expf(m - mp) + sp; m = mp; }
        else        { s += sp * expf(mp - m); }
    }
    __shared__ float sm[128], ss[128];
    sm[t] = m; ss[t] = s;
    __syncthreads();
    for (int stride = 64; stride > 0; stride >>= 1) {
        if (t < stride) {
            float m1 = sm[t], s1 = ss[t];
            float m2 = sm[t + stride], s2 = ss[t + stride];
            float M = fmaxf(m1, m2);
            ss[t] = s1 * expf(m1 - M) + s2 * expf(m2 - M);
            sm[t] = M;
        }
        __syncthreads();
    }
    if (t == 0) { g_M[row] = sm[0]; g_invZ[row] = 1.f / ss[0]; }
}

// ---------------------------------------------------------------------------
// Kernel D: in-place normalize: out = exp(logit - M) / Z   (float4)
// ---------------------------------------------------------------------------
__global__ void softmax_kernel(float* __restrict__ out) {
    unsigned int idx = blockIdx.x * blockDim.x + threadIdx.x;
    const unsigned int per_row = VOCABN / 4;
    unsigned int row = idx / per_row;
    float m = g_M[row];
    float z = g_invZ[row];
    float4 v = reinterpret_cast<float4*>(out)[idx];
    v.x = expf(v.x - m) * z;
    v.y = expf(v.y - m) * z;
    v.z = expf(v.z - m) * z;
    v.w = expf(v.w - m) * z;
    reinterpret_cast<float4*>(out)[idx] = v;
}

// ---------------------------------------------------------------------------
extern "C" void kernel_launch(void* const* d_in, const int* in_sizes, int n_in,
                              void* d_out, int out_size) {
    const int*   x     = (const int*)d_in[0];
    const float* noise = (const float*)d_in[1];
    const float* emb   = (const float*)d_in[2];
    const float* W_ih  = (const float*)d_in[3];
    /* d_in[4] = W_hh — dead: h0 == 0 */
    const float* b_ih  = (const float*)d_in[5];
    const float* b_hh  = (const float*)d_in[6];
    const float* fc_w  = (const float*)d_in[7];
    const float* fc_b  = (const float*)d_in[8];
    float* out = (float*)d_out;

    const int smemA = (384 * WPAD + A_ROWS * CIN) * 4;
    cudaFuncSetAttribute(lstm_kernel, cudaFuncAttributeMaxDynamicSharedMemorySize, smemA);
    cudaFuncSetAttribute(gemm_tc, cudaFuncAttributeMaxDynamicSharedMemorySize, SMEM_GEMM);

    convert_w_kernel<<<(NCH * 2048) / 256, 256>>>(fc_w);
    lstm_kernel<<<BATCH / A_ROWS, 256, smemA>>>(x, noise, emb, W_ih, b_ih, b_hh);
    convert_a_kernel<<<(MT16 * 2048) / 256, 256>>>();
    gemm_tc<<<NCH, 256, SMEM_GEMM>>>(fc_b, out);
    reduce_kernel<<<BATCH, 128>>>();
    softmax_kernel<<<(BATCH * (VOCABN / 4)) / 256, 256>>>(out);
}

// round 6
// speedup vs baseline: 3.5933x; 1.0965x over previous
#include <cuda_runtime.h>
#include <cuda_bf16.h>
#include <math.h>
#include <math_constants.h>
#include <cstdint>

// Problem constants
#define VOCABN 100000
#define EMBED  100
#define NOISEN 10
#define CIN    110
#define HID    128
#define BATCH  2048

// GEMM tiling
#define NCH 782                 // ceil(100000/128): vocab tiles of 128
#define MT16 16                 // 128-row A tiles
#define TILE_BYTES 32768        // 128x128 bf16 tile

// LSTM kernel tiling
#define A_ROWS 16
#define WPAD   111

// ---------------------------------------------------------------------------
// Scratch (static __device__, no allocations)
// ---------------------------------------------------------------------------
__device__ __align__(16) char g_B[(size_t)NCH * TILE_BYTES];     // 25.6 MB bf16 tiles
__device__ __align__(16) char g_A[MT16 * TILE_BYTES];            // 512 KB
__device__ float g_h[BATCH * HID];
__device__ float g_pmax[(size_t)BATCH * NCH];
__device__ float g_psum[(size_t)BATCH * NCH];
__device__ float g_M[BATCH];
__device__ float g_invZ[BATCH];

__device__ __forceinline__ float sigm(float v) { return 1.0f / (1.0f + expf(-v)); }

__device__ __forceinline__ uint32_t smem_to_u32(const void* p) {
    uint32_t a;
    asm("{ .reg .u64 t; cvta.to.shared.u64 t, %1; cvt.u32.u64 %0, t; }" : "=r"(a) : "l"(p));
    return a;
}

// Blocked-atom SW128 byte offset inside a 128x128 bf16 tile (conflict-free ldsm)
__host__ __device__ __forceinline__ uint32_t tile_off(int row, int col) {
    return (uint32_t)((((row >> 3) + ((col >> 6) << 4)) << 10) +
                      ((row & 7) << 7) + ((((col & 63) << 1)) ^ ((row & 7) << 4)));
}

__device__ __forceinline__ void ldsm_x4(uint32_t* r, uint32_t addr) {
    asm volatile("ldmatrix.sync.aligned.m8n8.x4.shared.b16 {%0,%1,%2,%3}, [%4];"
                 : "=r"(r[0]), "=r"(r[1]), "=r"(r[2]), "=r"(r[3]) : "r"(addr));
}

__device__ __forceinline__ void ldsm_block(uint32_t* r, uint32_t base, int row0, int col0, int lane) {
    int sub = lane >> 3, rr = lane & 7;
    int row = row0 + ((sub & 1) << 3) + rr;
    int col = col0 + ((sub >> 1) << 3);
    ldsm_x4(r, base + tile_off(row, col));
}

__device__ __forceinline__ void mma16816(float* c, const uint32_t* a, uint32_t b0, uint32_t b1) {
    asm volatile(
        "mma.sync.aligned.m16n8k16.row.col.f32.bf16.bf16.f32 "
        "{%0,%1,%2,%3}, {%4,%5,%6,%7}, {%8,%9}, {%0,%1,%2,%3};"
        : "+f"(c[0]), "+f"(c[1]), "+f"(c[2]), "+f"(c[3])
        : "r"(a[0]), "r"(a[1]), "r"(a[2]), "r"(a[3]), "r"(b0), "r"(b1));
}

__device__ __forceinline__ void cp_async16(uint32_t saddr, const void* gaddr) {
    asm volatile("cp.async.cg.shared.global [%0], [%1], 16;" :: "r"(saddr), "l"(gaddr));
}
#define CP_COMMIT() asm volatile("cp.async.commit_group;" ::: "memory")
#define CP_WAIT0()  asm volatile("cp.async.wait_group 0;" ::: "memory")

// ---------------------------------------------------------------------------
// Kernel A: embedding + noise + LSTM step -> g_h [2048, 128] fp32
// ---------------------------------------------------------------------------
__global__ void lstm_kernel(const int* __restrict__ x,
                            const float* __restrict__ noise,
                            const float* __restrict__ emb,
                            const float* __restrict__ W_ih,
                            const float* __restrict__ b_ih,
                            const float* __restrict__ b_hh) {
    extern __shared__ float sm[];
    float* Wsm = sm;                       // [384][WPAD]
    float* Csm = sm + 384 * WPAD;          // [A_ROWS][CIN]

    const int t = threadIdx.x;
    const int row0 = blockIdx.x * A_ROWS;

    for (int idx = t; idx < 384 * CIN; idx += 256) {
        int r = idx / CIN;
        int k = idx - r * CIN;
        int gr = (r < 128) ? r : (r + 128);   // skip dead f block
        Wsm[r * WPAD + k] = W_ih[gr * CIN + k];
    }
    for (int idx = t; idx < A_ROWS * CIN; idx += 256) {
        int r = idx / CIN;
        int k = idx - r * CIN;
        int brow = row0 + r;
        float v = (k < EMBED) ? emb[(size_t)x[brow] * EMBED + k]
                              : noise[brow * NOISEN + (k - EMBED)];
        Csm[r * CIN + k] = v;
    }
    __syncthreads();

    const int j = t & 127;
    const int rhalf = t >> 7;
    const float bi = b_ih[j]       + b_hh[j];
    const float bg = b_ih[256 + j] + b_hh[256 + j];
    const float bo = b_ih[384 + j] + b_hh[384 + j];

    const float* wi = &Wsm[j * WPAD];
    const float* wg = &Wsm[(128 + j) * WPAD];
    const float* wo = &Wsm[(256 + j) * WPAD];

    for (int rr = 0; rr < A_ROWS / 2; rr++) {
        int r = rhalf * (A_ROWS / 2) + rr;
        const float* c = &Csm[r * CIN];
        float ai = bi, ag = bg, ao = bo;
        #pragma unroll 2
        for (int k = 0; k < CIN; k++) {
            float cv = c[k];
            ai = fmaf(wi[k], cv, ai);
            ag = fmaf(wg[k], cv, ag);
            ao = fmaf(wo[k], cv, ao);
        }
        float cc = sigm(ai) * tanhf(ag);
        float h  = sigm(ao) * tanhf(cc);
        g_h[(row0 + r) * HID + j] = h;
    }
}

// ---------------------------------------------------------------------------
// Convert fc_w -> swizzled bf16 tiles (pad rows beyond VOCAB with 0)
// ---------------------------------------------------------------------------
__global__ void convert_w_kernel(const float* __restrict__ fc_w) {
    int c = blockIdx.x * blockDim.x + threadIdx.x;     // 16B-chunk id
    int tile = c >> 11;
    int q = c & 2047;
    int row = q >> 4;
    int kc = q & 15;
    int v = tile * 128 + row;

    float4 w0, w1;
    if (v < VOCABN) {
        const float4* src = reinterpret_cast<const float4*>(fc_w + (size_t)v * HID + kc * 8);
        w0 = src[0]; w1 = src[1];
    } else {
        w0 = w1 = make_float4(0.f, 0.f, 0.f, 0.f);
    }
    float f[8] = {w0.x, w0.y, w0.z, w0.w, w1.x, w1.y, w1.z, w1.w};
    __nv_bfloat16 hv[8];
    #pragma unroll
    for (int i = 0; i < 8; i++) hv[i] = __float2bfloat16(f[i]);
    size_t off = (size_t)tile * TILE_BYTES + tile_off(row, kc * 8);
    *reinterpret_cast<uint4*>(g_B + off) = *reinterpret_cast<uint4*>(hv);
}

// ---------------------------------------------------------------------------
// Convert g_h -> swizzled bf16 A tiles
// ---------------------------------------------------------------------------
__global__ void convert_a_kernel() {
    int c = blockIdx.x * blockDim.x + threadIdx.x;     // 16B-chunk id, 32768 total
    int tile = c >> 11;
    int q = c & 2047;
    int row = q >> 4;
    int kc = q & 15;
    const float4* src = reinterpret_cast<const float4*>(g_h + (size_t)(tile * 128 + row) * HID + kc * 8);
    float4 w0 = src[0], w1 = src[1];
    float f[8] = {w0.x, w0.y, w0.z, w0.w, w1.x, w1.y, w1.z, w1.w};
    __nv_bfloat16 hv[8];
    #pragma unroll
    for (int i = 0; i < 8; i++) hv[i] = __float2bfloat16(f[i]);
    size_t off = (size_t)tile * TILE_BYTES + tile_off(row, kc * 8);
    *reinterpret_cast<uint4*>(g_A + off) = *reinterpret_cast<uint4*>(hv);
}

// ---------------------------------------------------------------------------
// Shared GEMM skeleton: one vocab tile of B (N=128) resident, loop 16 M tiles,
// A double-buffered via cp.async. 8 warps = 4(M) x 2(N), warp tile 32x64.
// PHASE==1: emit softmax partials only. PHASE==2: write probs directly.
// ---------------------------------------------------------------------------
#define OFF_B     0              // 32 KB
#define OFF_A     32768          // 2 x 32 KB
#define OFF_BIAS  98304          // 512 B
#define OFF_REDM  98816          // 1 KB (phase1) / row -M (phase2)
#define OFF_REDS  99840          // 1 KB (phase1) / row invZ (phase2)
#define SMEM_GEMM 100864

template <int PHASE>
__global__ __launch_bounds__(256, 2) void gemm_tc(const float* __restrict__ fc_b,
                                                  float* __restrict__ out) {
    extern __shared__ char smem[];
    const int t = threadIdx.x, wid = t >> 5, lane = t & 31;
    const int vb = blockIdx.x;
    const uint32_t sb = smem_to_u32(smem);

    const int wm = wid >> 1;      // 0..3 : 32-row slab
    const int wn = wid & 1;       // 0..1 : 64-col slab
    const int g = lane >> 2, t4 = lane & 3;

    // Stage B tile + bias; start A[0] prefetch
    {
        const uint4* gb = reinterpret_cast<const uint4*>(g_B + (size_t)vb * TILE_BYTES);
        uint4* sbp = reinterpret_cast<uint4*>(smem + OFF_B);
        #pragma unroll
        for (int i = 0; i < 8; i++) sbp[t + 256 * i] = gb[t + 256 * i];
    }
    #pragma unroll
    for (int i = 0; i < 8; i++)
        cp_async16(sb + OFF_A + t * 16 + i * 4096, g_A + t * 16 + i * 4096);
    CP_COMMIT();
    if (t < 128) {
        int gc = vb * 128 + t;
        reinterpret_cast<float*>(smem + OFF_BIAS)[t] = (gc < VOCABN) ? fc_b[gc] : -CUDART_INF_F;
    }
    CP_WAIT0();
    __syncthreads();

    const uint32_t sB = sb + OFF_B;
    float* bias = reinterpret_cast<float*>(smem + OFF_BIAS);
    float* redm = reinterpret_cast<float*>(smem + OFF_REDM);   // phase2: -M per row
    float* reds = reinterpret_cast<float*>(smem + OFF_REDS);   // phase2: invZ per row

    const int am0 = wm * 32;
    const int bn0 = wn * 64;

    for (int mt = 0; mt < MT16; mt++) {
        // Prefetch next A tile into the other buffer
        if (mt + 1 < MT16) {
            uint32_t dst = sb + OFF_A + ((mt + 1) & 1) * TILE_BYTES;
            const char* src = g_A + (size_t)(mt + 1) * TILE_BYTES;
            #pragma unroll
            for (int i = 0; i < 8; i++)
                cp_async16(dst + t * 16 + i * 4096, src + t * 16 + i * 4096);
            CP_COMMIT();
        }
        const int mbase = mt * 128;

        // Phase 2: stage per-row -M and invZ for this M tile
        if (PHASE == 2) {
            if (t < 128) redm[t] = -g_M[mbase + t];
            else if (t < 256) reds[t - 128] = g_invZ[mbase + (t - 128)];
        }

        const uint32_t sA = sb + OFF_A + (mt & 1) * TILE_BYTES;

        float acc[2][8][4];
        #pragma unroll
        for (int mb = 0; mb < 2; mb++)
            #pragma unroll
            for (int nb = 0; nb < 8; nb++)
                #pragma unroll
                for (int r = 0; r < 4; r++) acc[mb][nb][r] = 0.f;

        #pragma unroll
        for (int ks = 0; ks < 8; ks++) {
            const int k0 = ks * 16;
            uint32_t a[2][4], b[4][4];
            #pragma unroll
            for (int mb = 0; mb < 2; mb++) ldsm_block(a[mb], sA, am0 + mb * 16, k0, lane);
            #pragma unroll
            for (int nbb = 0; nbb < 4; nbb++) ldsm_block(b[nbb], sB, bn0 + nbb * 16, k0, lane);
            #pragma unroll
            for (int mb = 0; mb < 2; mb++)
                #pragma unroll
                for (int nbb = 0; nbb < 4; nbb++) {
                    mma16816(acc[mb][2 * nbb],     a[mb], b[nbb][0], b[nbb][2]);
                    mma16816(acc[mb][2 * nbb + 1], a[mb], b[nbb][1], b[nbb][3]);
                }
        }

        if (PHASE == 2) __syncthreads();   // redm/reds staged vs. use

        if (PHASE == 1) {
            // ---- partials epilogue: max + sumexp per row over this vocab tile ----
            #pragma unroll
            for (int mb = 0; mb < 2; mb++) {
                #pragma unroll
                for (int h = 0; h < 2; h++) {
                    int rl = am0 + mb * 16 + h * 8 + g;
                    float mx = -CUDART_INF_F;
                    #pragma unroll
                    for (int nb = 0; nb < 8; nb++) {
                        int cl = bn0 + nb * 8 + t4 * 2;
                        float v0 = acc[mb][nb][h * 2]     + bias[cl];
                        float v1 = acc[mb][nb][h * 2 + 1] + bias[cl + 1];
                        acc[mb][nb][h * 2] = v0;
                        acc[mb][nb][h * 2 + 1] = v1;
                        mx = fmaxf(mx, fmaxf(v0, v1));
                    }
                    mx = fmaxf(mx, __shfl_xor_sync(0xffffffffu, mx, 1));
                    mx = fmaxf(mx, __shfl_xor_sync(0xffffffffu, mx, 2));
                    if (t4 == 0) redm[rl * 2 + wn] = mx;
                }
            }
            __syncthreads();
            #pragma unroll
            for (int mb = 0; mb < 2; mb++) {
                #pragma unroll
                for (int h = 0; h < 2; h++) {
                    int rl = am0 + mb * 16 + h * 8 + g;
                    float gm = fmaxf(redm[rl * 2], redm[rl * 2 + 1]);
                    float s = 0.f;
                    #pragma unroll
                    for (int nb = 0; nb < 8; nb++)
                        s += expf(acc[mb][nb][h * 2] - gm) + expf(acc[mb][nb][h * 2 + 1] - gm);
                    s += __shfl_xor_sync(0xffffffffu, s, 1);
                    s += __shfl_xor_sync(0xffffffffu, s, 2);
                    if (t4 == 0) reds[rl * 2 + wn] = s;
                }
            }
            __syncthreads();
            if (t < 128) {
                g_pmax[(size_t)(mbase + t) * NCH + vb] = fmaxf(redm[t * 2], redm[t * 2 + 1]);
                g_psum[(size_t)(mbase + t) * NCH + vb] = reds[t * 2] + reds[t * 2 + 1];
            }
        } else {
            // ---- probs epilogue: p = exp(v + bias - M) * invZ, direct STG ----
            #pragma unroll
            for (int mb = 0; mb < 2; mb++) {
                #pragma unroll
                for (int h = 0; h < 2; h++) {
                    int rl = am0 + mb * 16 + h * 8 + g;
                    float negM = redm[rl];
                    float iz = reds[rl];
                    size_t rb = (size_t)(mbase + rl) * VOCABN;
                    #pragma unroll
                    for (int nb = 0; nb < 8; nb++) {
                        int cl = bn0 + nb * 8 + t4 * 2;
                        int gcol = vb * 128 + cl;
                        if (gcol < VOCABN) {
                            float p0 = expf(acc[mb][nb][h * 2]     + bias[cl]     + negM) * iz;
                            float p1 = expf(acc[mb][nb][h * 2 + 1] + bias[cl + 1] + negM) * iz;
                            *reinterpret_cast<float2*>(out + rb + gcol) = make_float2(p0, p1);
                        }
                    }
                }
            }
        }
        CP_WAIT0();
        __syncthreads();
    }
}

// ---------------------------------------------------------------------------
// Kernel C: per-row log-sum-exp merge of NCH partials -> M, 1/Z
// ---------------------------------------------------------------------------
__global__ void reduce_kernel() {
    const int row = blockIdx.x;
    const int t = threadIdx.x;    // 128
    float m = -CUDART_INF_F, s = 0.f;
    for (int p = t; p < NCH; p += 128) {
        float mp = g_pmax[(size_t)row * NCH + p];
        float sp = g_psum[(size_t)row * NCH + p];
        if (mp > m) { s = s * expf(m - mp) + sp; m = mp; }
        else        { s += sp * expf(mp - m); }
    }
    __shared__ float sm[128], ss[128];
    sm[t] = m; ss[t] = s;
    __syncthreads();
    for (int stride = 64; stride > 0; stride >>= 1) {
        if (t < stride) {
            float m1 = sm[t], s1 = ss[t];
            float m2 = sm[t + stride], s2 = ss[t + stride];
            float M = fmaxf(m1, m2);
            ss[t] = s1 * expf(m1 - M) + s2 * expf(m2 - M);
            sm[t] = M;
        }
        __syncthreads();
    }
    if (t == 0) { g_M[row] = sm[0]; g_invZ[row] = 1.f / ss[0]; }
}

// ---------------------------------------------------------------------------
extern "C" void kernel_launch(void* const* d_in, const int* in_sizes, int n_in,
                              void* d_out, int out_size) {
    const int*   x     = (const int*)d_in[0];
    const float* noise = (const float*)d_in[1];
    const float* emb   = (const float*)d_in[2];
    const float* W_ih  = (const float*)d_in[3];
    /* d_in[4] = W_hh — dead: h0 == 0 */
    const float* b_ih  = (const float*)d_in[5];
    const float* b_hh  = (const float*)d_in[6];
    const float* fc_w  = (const float*)d_in[7];
    const float* fc_b  = (const float*)d_in[8];
    float* out = (float*)d_out;

    const int smemA = (384 * WPAD + A_ROWS * CIN) * 4;
    cudaFuncSetAttribute(lstm_kernel, cudaFuncAttributeMaxDynamicSharedMemorySize, smemA);
    cudaFuncSetAttribute(gemm_tc<1>, cudaFuncAttributeMaxDynamicSharedMemorySize, SMEM_GEMM);
    cudaFuncSetAttribute(gemm_tc<2>, cudaFuncAttributeMaxDynamicSharedMemorySize, SMEM_GEMM);

    convert_w_kernel<<<(NCH * 2048) / 256, 256>>>(fc_w);
    lstm_kernel<<<BATCH / A_ROWS, 256, smemA>>>(x, noise, emb, W_ih, b_ih, b_hh);
    convert_a_kernel<<<(MT16 * 2048) / 256, 256>>>();
    gemm_tc<1><<<NCH, 256, SMEM_GEMM>>>(fc_b, out);
    reduce_kernel<<<BATCH, 128>>>();
    gemm_tc<2><<<NCH, 256, SMEM_GEMM>>>(fc_b, out);
}

// round 7
// speedup vs baseline: 3.7832x; 1.0529x over previous
#include <cuda_runtime.h>
#include <cuda_bf16.h>
#include <math.h>
#include <math_constants.h>
#include <cstdint>

// Problem constants
#define VOCABN 100000
#define EMBED  100
#define NOISEN 10
#define CIN    110
#define HID    128
#define BATCH  2048

// GEMM tiling
#define NCH 782                 // ceil(100000/128): vocab tiles of 128
#define NCHP (2 * NCH)          // partials per row (two wn halves per tile)
#define MT16 16                 // 128-row A tiles
#define TILE_BYTES 32768        // 128x128 bf16 tile

// LSTM kernel tiling
#define A_ROWS 16
#define WPAD   111

// ---------------------------------------------------------------------------
// Scratch (static __device__, no allocations)
// ---------------------------------------------------------------------------
__device__ __align__(16) char g_B[(size_t)NCH * TILE_BYTES];     // 25.6 MB bf16 tiles
__device__ __align__(16) char g_A[MT16 * TILE_BYTES];            // 512 KB
__device__ float g_h[BATCH * HID];
__device__ float g_psum[(size_t)BATCH * NCHP];                   // 12.8 MB
__device__ float g_invZ[BATCH];

__device__ __forceinline__ float sigm(float v) { return 1.0f / (1.0f + expf(-v)); }

__device__ __forceinline__ uint32_t smem_to_u32(const void* p) {
    uint32_t a;
    asm("{ .reg .u64 t; cvta.to.shared.u64 t, %1; cvt.u32.u64 %0, t; }" : "=r"(a) : "l"(p));
    return a;
}

// Blocked-atom SW128 byte offset inside a 128x128 bf16 tile (conflict-free ldsm)
__host__ __device__ __forceinline__ uint32_t tile_off(int row, int col) {
    return (uint32_t)((((row >> 3) + ((col >> 6) << 4)) << 10) +
                      ((row & 7) << 7) + ((((col & 63) << 1)) ^ ((row & 7) << 4)));
}

__device__ __forceinline__ void ldsm_x4(uint32_t* r, uint32_t addr) {
    asm volatile("ldmatrix.sync.aligned.m8n8.x4.shared.b16 {%0,%1,%2,%3}, [%4];"
                 : "=r"(r[0]), "=r"(r[1]), "=r"(r[2]), "=r"(r[3]) : "r"(addr));
}

__device__ __forceinline__ void ldsm_block(uint32_t* r, uint32_t base, int row0, int col0, int lane) {
    int sub = lane >> 3, rr = lane & 7;
    int row = row0 + ((sub & 1) << 3) + rr;
    int col = col0 + ((sub >> 1) << 3);
    ldsm_x4(r, base + tile_off(row, col));
}

__device__ __forceinline__ void mma16816(float* c, const uint32_t* a, uint32_t b0, uint32_t b1) {
    asm volatile(
        "mma.sync.aligned.m16n8k16.row.col.f32.bf16.bf16.f32 "
        "{%0,%1,%2,%3}, {%4,%5,%6,%7}, {%8,%9}, {%0,%1,%2,%3};"
        : "+f"(c[0]), "+f"(c[1]), "+f"(c[2]), "+f"(c[3])
        : "r"(a[0]), "r"(a[1]), "r"(a[2]), "r"(a[3]), "r"(b0), "r"(b1));
}

__device__ __forceinline__ void cp_async16(uint32_t saddr, const void* gaddr) {
    asm volatile("cp.async.cg.shared.global [%0], [%1], 16;" :: "r"(saddr), "l"(gaddr));
}
#define CP_COMMIT() asm volatile("cp.async.commit_group;" ::: "memory")
#define CP_WAIT0()  asm volatile("cp.async.wait_group 0;" ::: "memory")

// ---------------------------------------------------------------------------
// Kernel A: embedding + noise + LSTM step -> g_h [2048, 128] fp32
// ---------------------------------------------------------------------------
__global__ void lstm_kernel(const int* __restrict__ x,
                            const float* __restrict__ noise,
                            const float* __restrict__ emb,
                            const float* __restrict__ W_ih,
                            const float* __restrict__ b_ih,
                            const float* __restrict__ b_hh) {
    extern __shared__ float sm[];
    float* Wsm = sm;                       // [384][WPAD]
    float* Csm = sm + 384 * WPAD;          // [A_ROWS][CIN]

    const int t = threadIdx.x;
    const int row0 = blockIdx.x * A_ROWS;

    for (int idx = t; idx < 384 * CIN; idx += 256) {
        int r = idx / CIN;
        int k = idx - r * CIN;
        int gr = (r < 128) ? r : (r + 128);   // skip dead f block
        Wsm[r * WPAD + k] = W_ih[gr * CIN + k];
    }
    for (int idx = t; idx < A_ROWS * CIN; idx += 256) {
        int r = idx / CIN;
        int k = idx - r * CIN;
        int brow = row0 + r;
        float v = (k < EMBED) ? emb[(size_t)x[brow] * EMBED + k]
                              : noise[brow * NOISEN + (k - EMBED)];
        Csm[r * CIN + k] = v;
    }
    __syncthreads();

    const int j = t & 127;
    const int rhalf = t >> 7;
    const float bi = b_ih[j]       + b_hh[j];
    const float bg = b_ih[256 + j] + b_hh[256 + j];
    const float bo = b_ih[384 + j] + b_hh[384 + j];

    const float* wi = &Wsm[j * WPAD];
    const float* wg = &Wsm[(128 + j) * WPAD];
    const float* wo = &Wsm[(256 + j) * WPAD];

    for (int rr = 0; rr < A_ROWS / 2; rr++) {
        int r = rhalf * (A_ROWS / 2) + rr;
        const float* c = &Csm[r * CIN];
        float ai = bi, ag = bg, ao = bo;
        #pragma unroll 2
        for (int k = 0; k < CIN; k++) {
            float cv = c[k];
            ai = fmaf(wi[k], cv, ai);
            ag = fmaf(wg[k], cv, ag);
            ao = fmaf(wo[k], cv, ao);
        }
        float cc = sigm(ai) * tanhf(ag);
        float h  = sigm(ao) * tanhf(cc);
        g_h[(row0 + r) * HID + j] = h;
    }
}

// ---------------------------------------------------------------------------
// Convert fc_w -> swizzled bf16 tiles (pad rows beyond VOCAB with 0)
// ---------------------------------------------------------------------------
__global__ void convert_w_kernel(const float* __restrict__ fc_w) {
    int c = blockIdx.x * blockDim.x + threadIdx.x;     // 16B-chunk id
    int tile = c >> 11;
    int q = c & 2047;
    int row = q >> 4;
    int kc = q & 15;
    int v = tile * 128 + row;

    float4 w0, w1;
    if (v < VOCABN) {
        const float4* src = reinterpret_cast<const float4*>(fc_w + (size_t)v * HID + kc * 8);
        w0 = src[0]; w1 = src[1];
    } else {
        w0 = w1 = make_float4(0.f, 0.f, 0.f, 0.f);
    }
    float f[8] = {w0.x, w0.y, w0.z, w0.w, w1.x, w1.y, w1.z, w1.w};
    __nv_bfloat16 hv[8];
    #pragma unroll
    for (int i = 0; i < 8; i++) hv[i] = __float2bfloat16(f[i]);
    size_t off = (size_t)tile * TILE_BYTES + tile_off(row, kc * 8);
    *reinterpret_cast<uint4*>(g_B + off) = *reinterpret_cast<uint4*>(hv);
}

// ---------------------------------------------------------------------------
// Convert g_h -> swizzled bf16 A tiles
// ---------------------------------------------------------------------------
__global__ void convert_a_kernel() {
    int c = blockIdx.x * blockDim.x + threadIdx.x;     // 16B-chunk id, 32768 total
    int tile = c >> 11;
    int q = c & 2047;
    int row = q >> 4;
    int kc = q & 15;
    const float4* src = reinterpret_cast<const float4*>(g_h + (size_t)(tile * 128 + row) * HID + kc * 8);
    float4 w0 = src[0], w1 = src[1];
    float f[8] = {w0.x, w0.y, w0.z, w0.w, w1.x, w1.y, w1.z, w1.w};
    __nv_bfloat16 hv[8];
    #pragma unroll
    for (int i = 0; i < 8; i++) hv[i] = __float2bfloat16(f[i]);
    size_t off = (size_t)tile * TILE_BYTES + tile_off(row, kc * 8);
    *reinterpret_cast<uint4*>(g_A + off) = *reinterpret_cast<uint4*>(hv);
}

// ---------------------------------------------------------------------------
// Shared GEMM skeleton, no-max softmax.
// PHASE==1: per-(row, wn-half) sumexp partials only (no smem reductions).
// PHASE==2: p = exp(v + bias) * invZ written directly to out.
// ---------------------------------------------------------------------------
#define OFF_B     0              // 32 KB
#define OFF_A     32768          // 2 x 32 KB
#define OFF_BIAS  98304          // 512 B
#define SMEM_GEMM 98816

template <int PHASE>
__global__ __launch_bounds__(256, 2) void gemm_tc(const float* __restrict__ fc_b,
                                                  float* __restrict__ out) {
    extern __shared__ char smem[];
    const int t = threadIdx.x, wid = t >> 5, lane = t & 31;
    const int vb = blockIdx.x;
    const uint32_t sb = smem_to_u32(smem);

    const int wm = wid >> 1;      // 0..3 : 32-row slab
    const int wn = wid & 1;       // 0..1 : 64-col slab
    const int g = lane >> 2, t4 = lane & 3;

    // Stage B tile + bias; start A[0] prefetch
    {
        const uint4* gb = reinterpret_cast<const uint4*>(g_B + (size_t)vb * TILE_BYTES);
        uint4* sbp = reinterpret_cast<uint4*>(smem + OFF_B);
        #pragma unroll
        for (int i = 0; i < 8; i++) sbp[t + 256 * i] = gb[t + 256 * i];
    }
    #pragma unroll
    for (int i = 0; i < 8; i++)
        cp_async16(sb + OFF_A + t * 16 + i * 4096, g_A + t * 16 + i * 4096);
    CP_COMMIT();
    if (t < 128) {
        int gc = vb * 128 + t;
        reinterpret_cast<float*>(smem + OFF_BIAS)[t] = (gc < VOCABN) ? fc_b[gc] : -CUDART_INF_F;
    }
    CP_WAIT0();
    __syncthreads();

    const uint32_t sB = sb + OFF_B;
    const int am0 = wm * 32;
    const int bn0 = wn * 64;

    // Hoist bias into registers (constant over all M tiles)
    float bb0[8], bb1[8];
    {
        const float* bias = reinterpret_cast<const float*>(smem + OFF_BIAS);
        #pragma unroll
        for (int nb = 0; nb < 8; nb++) {
            bb0[nb] = bias[bn0 + nb * 8 + t4 * 2];
            bb1[nb] = bias[bn0 + nb * 8 + t4 * 2 + 1];
        }
    }

    const bool full_tile = (vb < NCH - 1);

    for (int mt = 0; mt < MT16; mt++) {
        if (mt + 1 < MT16) {
            uint32_t dst = sb + OFF_A + ((mt + 1) & 1) * TILE_BYTES;
            const char* src = g_A + (size_t)(mt + 1) * TILE_BYTES;
            #pragma unroll
            for (int i = 0; i < 8; i++)
                cp_async16(dst + t * 16 + i * 4096, src + t * 16 + i * 4096);
            CP_COMMIT();
        }
        const int mbase = mt * 128;
        const uint32_t sA = sb + OFF_A + (mt & 1) * TILE_BYTES;

        float acc[2][8][4];
        #pragma unroll
        for (int mb = 0; mb < 2; mb++)
            #pragma unroll
            for (int nb = 0; nb < 8; nb++)
                #pragma unroll
                for (int r = 0; r < 4; r++) acc[mb][nb][r] = 0.f;

        #pragma unroll
        for (int ks = 0; ks < 8; ks++) {
            const int k0 = ks * 16;
            uint32_t a[2][4], b[4][4];
            #pragma unroll
            for (int mb = 0; mb < 2; mb++) ldsm_block(a[mb], sA, am0 + mb * 16, k0, lane);
            #pragma unroll
            for (int nbb = 0; nbb < 4; nbb++) ldsm_block(b[nbb], sB, bn0 + nbb * 16, k0, lane);
            #pragma unroll
            for (int mb = 0; mb < 2; mb++)
                #pragma unroll
                for (int nbb = 0; nbb < 4; nbb++) {
                    mma16816(acc[mb][2 * nbb],     a[mb], b[nbb][0], b[nbb][2]);
                    mma16816(acc[mb][2 * nbb + 1], a[mb], b[nbb][1], b[nbb][3]);
                }
        }

        if (PHASE == 1) {
            // ---- sumexp partial per (row, wn-half); no smem, no extra syncs ----
            #pragma unroll
            for (int mb = 0; mb < 2; mb++) {
                #pragma unroll
                for (int h = 0; h < 2; h++) {
                    int rl = am0 + mb * 16 + h * 8 + g;
                    float s = 0.f;
                    #pragma unroll
                    for (int nb = 0; nb < 8; nb++)
                        s += expf(acc[mb][nb][h * 2] + bb0[nb]) +
                             expf(acc[mb][nb][h * 2 + 1] + bb1[nb]);
                    s += __shfl_xor_sync(0xffffffffu, s, 1);
                    s += __shfl_xor_sync(0xffffffffu, s, 2);
                    if (t4 == 0)
                        g_psum[(size_t)(mbase + rl) * NCHP + vb * 2 + wn] = s;
                }
            }
        } else {
            // ---- probs: p = exp(v + bias) * invZ, direct STG ----
            #pragma unroll
            for (int mb = 0; mb < 2; mb++) {
                #pragma unroll
                for (int h = 0; h < 2; h++) {
                    int rl = am0 + mb * 16 + h * 8 + g;
                    float iz = __ldg(&g_invZ[mbase + rl]);
                    size_t rb = (size_t)(mbase + rl) * VOCABN + vb * 128;
                    if (full_tile) {
                        #pragma unroll
                        for (int nb = 0; nb < 8; nb++) {
                            int cl = bn0 + nb * 8 + t4 * 2;
                            float p0 = expf(acc[mb][nb][h * 2]     + bb0[nb]) * iz;
                            float p1 = expf(acc[mb][nb][h * 2 + 1] + bb1[nb]) * iz;
                            *reinterpret_cast<float2*>(out + rb + cl) = make_float2(p0, p1);
                        }
                    } else {
                        #pragma unroll
                        for (int nb = 0; nb < 8; nb++) {
                            int cl = bn0 + nb * 8 + t4 * 2;
                            if (vb * 128 + cl < VOCABN) {
                                float p0 = expf(acc[mb][nb][h * 2]     + bb0[nb]) * iz;
                                float p1 = expf(acc[mb][nb][h * 2 + 1] + bb1[nb]) * iz;
                                *reinterpret_cast<float2*>(out + rb + cl) = make_float2(p0, p1);
                            }
                        }
                    }
                }
            }
        }
        CP_WAIT0();
        __syncthreads();
    }
}

// ---------------------------------------------------------------------------
// Kernel C: per-row plain sum of NCHP partials -> invZ
// ---------------------------------------------------------------------------
__global__ void reduce_kernel() {
    const int row = blockIdx.x;
    const int t = threadIdx.x;    // 256
    float s = 0.f;
    const float* p = &g_psum[(size_t)row * NCHP];
    for (int i = t; i < NCHP; i += 256) s += p[i];
    __shared__ float ss[256];
    ss[t] = s;
    __syncthreads();
    for (int stride = 128; stride > 0; stride >>= 1) {
        if (t < stride) ss[t] += ss[t + stride];
        __syncthreads();
    }
    if (t == 0) g_invZ[row] = 1.f / ss[0];
}

// ---------------------------------------------------------------------------
extern "C" void kernel_launch(void* const* d_in, const int* in_sizes, int n_in,
                              void* d_out, int out_size) {
    const int*   x     = (const int*)d_in[0];
    const float* noise = (const float*)d_in[1];
    const float* emb   = (const float*)d_in[2];
    const float* W_ih  = (const float*)d_in[3];
    /* d_in[4] = W_hh — dead: h0 == 0 */
    const float* b_ih  = (const float*)d_in[5];
    const float* b_hh  = (const float*)d_in[6];
    const float* fc_w  = (const float*)d_in[7];
    const float* fc_b  = (const float*)d_in[8];
    float* out = (float*)d_out;

    const int smemA = (384 * WPAD + A_ROWS * CIN) * 4;
    cudaFuncSetAttribute(lstm_kernel, cudaFuncAttributeMaxDynamicSharedMemorySize, smemA);
    cudaFuncSetAttribute(gemm_tc<1>, cudaFuncAttributeMaxDynamicSharedMemorySize, SMEM_GEMM);
    cudaFuncSetAttribute(gemm_tc<2>, cudaFuncAttributeMaxDynamicSharedMemorySize, SMEM_GEMM);

    convert_w_kernel<<<(NCH * 2048) / 256, 256>>>(fc_w);
    lstm_kernel<<<BATCH / A_ROWS, 256, smemA>>>(x, noise, emb, W_ih, b_ih, b_hh);
    convert_a_kernel<<<(MT16 * 2048) / 256, 256>>>();
    gemm_tc<1><<<NCH, 256, SMEM_GEMM>>>(fc_b, out);
    reduce_kernel<<<BATCH, 256>>>();
    gemm_tc<2><<<NCH, 256, SMEM_GEMM>>>(fc_b, out);
}

// round 8
// speedup vs baseline: 4.3243x; 1.1430x over previous
#include <cuda_runtime.h>
#include <cuda_bf16.h>
#include <math.h>
#include <math_constants.h>
#include <cstdint>

// Problem constants
#define VOCABN 100000
#define EMBED  100
#define NOISEN 10
#define CIN    110
#define HID    128
#define BATCH  2048

// GEMM tiling
#define NCH 782                 // ceil(100000/128): vocab tiles of 128
#define NCHP (2 * NCH)          // partials per row (two wn halves per tile)
#define MT16 16                 // 128-row A tiles
#define TILE_BYTES 32768        // 128x128 bf16 tile

// LSTM kernel tiling
#define A_ROWS 16
#define WPAD   111

// ---------------------------------------------------------------------------
// Scratch (static __device__, no allocations)
// ---------------------------------------------------------------------------
__device__ __align__(16) char g_B[(size_t)NCH * TILE_BYTES];     // 25.6 MB bf16 tiles
__device__ __align__(16) char g_A[MT16 * TILE_BYTES];            // 512 KB
__device__ float g_h[BATCH * HID];
__device__ float g_psum[(size_t)BATCH * NCHP];                   // 12.8 MB
__device__ float g_invZ[BATCH];

__device__ __forceinline__ float sigm(float v) { return 1.0f / (1.0f + expf(-v)); }

__device__ __forceinline__ uint32_t smem_to_u32(const void* p) {
    uint32_t a;
    asm("{ .reg .u64 t; cvta.to.shared.u64 t, %1; cvt.u32.u64 %0, t; }" : "=r"(a) : "l"(p));
    return a;
}

// Blocked-atom SW128 byte offset inside a 128x128 bf16 tile (conflict-free ldsm)
__host__ __device__ __forceinline__ uint32_t tile_off(int row, int col) {
    return (uint32_t)((((row >> 3) + ((col >> 6) << 4)) << 10) +
                      ((row & 7) << 7) + ((((col & 63) << 1)) ^ ((row & 7) << 4)));
}

__device__ __forceinline__ void ldsm_x4(uint32_t* r, uint32_t addr) {
    asm volatile("ldmatrix.sync.aligned.m8n8.x4.shared.b16 {%0,%1,%2,%3}, [%4];"
                 : "=r"(r[0]), "=r"(r[1]), "=r"(r[2]), "=r"(r[3]) : "r"(addr));
}

__device__ __forceinline__ void mma16816(float* c, const uint32_t* a, uint32_t b0, uint32_t b1) {
    asm volatile(
        "mma.sync.aligned.m16n8k16.row.col.f32.bf16.bf16.f32 "
        "{%0,%1,%2,%3}, {%4,%5,%6,%7}, {%8,%9}, {%0,%1,%2,%3};"
        : "+f"(c[0]), "+f"(c[1]), "+f"(c[2]), "+f"(c[3])
        : "r"(a[0]), "r"(a[1]), "r"(a[2]), "r"(a[3]), "r"(b0), "r"(b1));
}

__device__ __forceinline__ void cp_async16(uint32_t saddr, const void* gaddr) {
    asm volatile("cp.async.cg.shared.global [%0], [%1], 16;" :: "r"(saddr), "l"(gaddr));
}
#define CP_COMMIT() asm volatile("cp.async.commit_group;" ::: "memory")
#define CP_WAIT0()  asm volatile("cp.async.wait_group 0;" ::: "memory")

// K-step address transform: within an atom column the 16-col step XORs bits
// [5:6]; crossing to cols >= 64 adds one atom-column (16384 bytes).
#define KADDR(base, ks) ((((ks) >= 4) ? ((base) + 16384u) : (base)) ^ (uint32_t)(((ks) & 3) << 5))

// ---------------------------------------------------------------------------
// Kernel A: embedding + noise + LSTM step -> g_h [2048, 128] fp32
// ---------------------------------------------------------------------------
__global__ void lstm_kernel(const int* __restrict__ x,
                            const float* __restrict__ noise,
                            const float* __restrict__ emb,
                            const float* __restrict__ W_ih,
                            const float* __restrict__ b_ih,
                            const float* __restrict__ b_hh) {
    extern __shared__ float sm[];
    float* Wsm = sm;                       // [384][WPAD]
    float* Csm = sm + 384 * WPAD;          // [A_ROWS][CIN]

    const int t = threadIdx.x;
    const int row0 = blockIdx.x * A_ROWS;

    for (int idx = t; idx < 384 * CIN; idx += 256) {
        int r = idx / CIN;
        int k = idx - r * CIN;
        int gr = (r < 128) ? r : (r + 128);   // skip dead f block
        Wsm[r * WPAD + k] = W_ih[gr * CIN + k];
    }
    for (int idx = t; idx < A_ROWS * CIN; idx += 256) {
        int r = idx / CIN;
        int k = idx - r * CIN;
        int brow = row0 + r;
        float v = (k < EMBED) ? emb[(size_t)x[brow] * EMBED + k]
                              : noise[brow * NOISEN + (k - EMBED)];
        Csm[r * CIN + k] = v;
    }
    __syncthreads();

    const int j = t & 127;
    const int rhalf = t >> 7;
    const float bi = b_ih[j]       + b_hh[j];
    const float bg = b_ih[256 + j] + b_hh[256 + j];
    const float bo = b_ih[384 + j] + b_hh[384 + j];

    const float* wi = &Wsm[j * WPAD];
    const float* wg = &Wsm[(128 + j) * WPAD];
    const float* wo = &Wsm[(256 + j) * WPAD];

    for (int rr = 0; rr < A_ROWS / 2; rr++) {
        int r = rhalf * (A_ROWS / 2) + rr;
        const float* c = &Csm[r * CIN];
        float ai = bi, ag = bg, ao = bo;
        #pragma unroll 2
        for (int k = 0; k < CIN; k++) {
            float cv = c[k];
            ai = fmaf(wi[k], cv, ai);
            ag = fmaf(wg[k], cv, ag);
            ao = fmaf(wo[k], cv, ao);
        }
        float cc = sigm(ai) * tanhf(ag);
        float h  = sigm(ao) * tanhf(cc);
        g_h[(row0 + r) * HID + j] = h;
    }
}

// ---------------------------------------------------------------------------
// Convert fc_w -> swizzled bf16 tiles (pad rows beyond VOCAB with 0)
// ---------------------------------------------------------------------------
__global__ void convert_w_kernel(const float* __restrict__ fc_w) {
    int c = blockIdx.x * blockDim.x + threadIdx.x;     // 16B-chunk id
    int tile = c >> 11;
    int q = c & 2047;
    int row = q >> 4;
    int kc = q & 15;
    int v = tile * 128 + row;

    float4 w0, w1;
    if (v < VOCABN) {
        const float4* src = reinterpret_cast<const float4*>(fc_w + (size_t)v * HID + kc * 8);
        w0 = src[0]; w1 = src[1];
    } else {
        w0 = w1 = make_float4(0.f, 0.f, 0.f, 0.f);
    }
    float f[8] = {w0.x, w0.y, w0.z, w0.w, w1.x, w1.y, w1.z, w1.w};
    __nv_bfloat16 hv[8];
    #pragma unroll
    for (int i = 0; i < 8; i++) hv[i] = __float2bfloat16(f[i]);
    size_t off = (size_t)tile * TILE_BYTES + tile_off(row, kc * 8);
    *reinterpret_cast<uint4*>(g_B + off) = *reinterpret_cast<uint4*>(hv);
}

// ---------------------------------------------------------------------------
// Convert g_h -> swizzled bf16 A tiles
// ---------------------------------------------------------------------------
__global__ void convert_a_kernel() {
    int c = blockIdx.x * blockDim.x + threadIdx.x;     // 16B-chunk id, 32768 total
    int tile = c >> 11;
    int q = c & 2047;
    int row = q >> 4;
    int kc = q & 15;
    const float4* src = reinterpret_cast<const float4*>(g_h + (size_t)(tile * 128 + row) * HID + kc * 8);
    float4 w0 = src[0], w1 = src[1];
    float f[8] = {w0.x, w0.y, w0.z, w0.w, w1.x, w1.y, w1.z, w1.w};
    __nv_bfloat16 hv[8];
    #pragma unroll
    for (int i = 0; i < 8; i++) hv[i] = __float2bfloat16(f[i]);
    size_t off = (size_t)tile * TILE_BYTES + tile_off(row, kc * 8);
    *reinterpret_cast<uint4*>(g_A + off) = *reinterpret_cast<uint4*>(hv);
}

// ---------------------------------------------------------------------------
// Shared GEMM skeleton, no-max softmax, hoisted ldsm addressing.
// PHASE==1: per-(row, wn-half) sumexp partials. PHASE==2: probs direct.
// ---------------------------------------------------------------------------
#define OFF_B     0              // 32 KB
#define OFF_A     32768          // 2 x 32 KB
#define OFF_BIAS  98304          // 512 B
#define SMEM_GEMM 98816

template <int PHASE>
__global__ __launch_bounds__(256, 2) void gemm_tc(const float* __restrict__ fc_b,
                                                  float* __restrict__ out) {
    extern __shared__ char smem[];
    const int t = threadIdx.x, wid = t >> 5, lane = t & 31;
    const int vb = blockIdx.x;
    const uint32_t sb = smem_to_u32(smem);

    const int wm = wid >> 1;      // 0..3 : 32-row slab
    const int wn = wid & 1;       // 0..1 : 64-col slab
    const int g = lane >> 2, t4 = lane & 3;

    // Stage B tile + bias; start A[0] prefetch
    {
        const uint4* gb = reinterpret_cast<const uint4*>(g_B + (size_t)vb * TILE_BYTES);
        uint4* sbp = reinterpret_cast<uint4*>(smem + OFF_B);
        #pragma unroll
        for (int i = 0; i < 8; i++) sbp[t + 256 * i] = gb[t + 256 * i];
    }
    #pragma unroll
    for (int i = 0; i < 8; i++)
        cp_async16(sb + OFF_A + t * 16 + i * 4096, g_A + t * 16 + i * 4096);
    CP_COMMIT();
    if (t < 128) {
        int gc = vb * 128 + t;
        reinterpret_cast<float*>(smem + OFF_BIAS)[t] = (gc < VOCABN) ? fc_b[gc] : -CUDART_INF_F;
    }
    CP_WAIT0();
    __syncthreads();

    const int am0 = wm * 32;
    const int bn0 = wn * 64;

    // Hoisted ldsm base addresses (ks = 0, mb = nbb = 0).
    // Per-mb / per-nbb stride: +16 rows = +2 atom-rows = +2048 bytes.
    const int sub = lane >> 3, rr = lane & 7;
    const int lrow = ((sub & 1) << 3) + rr;       // row within 16-row block
    const int colp = (sub >> 1) << 3;             // 0 or 8
    const uint32_t baseA0 = sb + OFF_A + tile_off(am0 + lrow, colp);
    const uint32_t baseB  = sb + OFF_B + tile_off(bn0 + lrow, colp);

    // Hoist bias into registers
    float bb0[8], bb1[8];
    {
        const float* bias = reinterpret_cast<const float*>(smem + OFF_BIAS);
        #pragma unroll
        for (int nb = 0; nb < 8; nb++) {
            bb0[nb] = bias[bn0 + nb * 8 + t4 * 2];
            bb1[nb] = bias[bn0 + nb * 8 + t4 * 2 + 1];
        }
    }

    const bool full_tile = (vb < NCH - 1);

    for (int mt = 0; mt < MT16; mt++) {
        if (mt + 1 < MT16) {
            uint32_t dst = sb + OFF_A + ((mt + 1) & 1) * TILE_BYTES;
            const char* src = g_A + (size_t)(mt + 1) * TILE_BYTES;
            #pragma unroll
            for (int i = 0; i < 8; i++)
                cp_async16(dst + t * 16 + i * 4096, src + t * 16 + i * 4096);
            CP_COMMIT();
        }
        const int mbase = mt * 128;
        const uint32_t baseA = baseA0 + (mt & 1) * TILE_BYTES;

        float acc[2][8][4];
        #pragma unroll
        for (int mb = 0; mb < 2; mb++)
            #pragma unroll
            for (int nb = 0; nb < 8; nb++)
                #pragma unroll
                for (int r = 0; r < 4; r++) acc[mb][nb][r] = 0.f;

        #pragma unroll
        for (int ks = 0; ks < 8; ks++) {
            uint32_t a[2][4], b[4][4];
            #pragma unroll
            for (int mb = 0; mb < 2; mb++)
                ldsm_x4(a[mb], KADDR(baseA + mb * 2048, ks));
            #pragma unroll
            for (int nbb = 0; nbb < 4; nbb++)
                ldsm_x4(b[nbb], KADDR(baseB + nbb * 2048, ks));
            #pragma unroll
            for (int mb = 0; mb < 2; mb++)
                #pragma unroll
                for (int nbb = 0; nbb < 4; nbb++) {
                    mma16816(acc[mb][2 * nbb],     a[mb], b[nbb][0], b[nbb][2]);
                    mma16816(acc[mb][2 * nbb + 1], a[mb], b[nbb][1], b[nbb][3]);
                }
        }

        if (PHASE == 1) {
            // ---- sumexp partial per (row, wn-half) ----
            #pragma unroll
            for (int mb = 0; mb < 2; mb++) {
                #pragma unroll
                for (int h = 0; h < 2; h++) {
                    int rl = am0 + mb * 16 + h * 8 + g;
                    float s = 0.f;
                    #pragma unroll
                    for (int nb = 0; nb < 8; nb++)
                        s += __expf(acc[mb][nb][h * 2] + bb0[nb]) +
                             __expf(acc[mb][nb][h * 2 + 1] + bb1[nb]);
                    s += __shfl_xor_sync(0xffffffffu, s, 1);
                    s += __shfl_xor_sync(0xffffffffu, s, 2);
                    if (t4 == 0)
                        g_psum[(size_t)(mbase + rl) * NCHP + vb * 2 + wn] = s;
                }
            }
        } else {
            // ---- probs: p = exp(v + bias) * invZ, direct STG ----
            #pragma unroll
            for (int mb = 0; mb < 2; mb++) {
                #pragma unroll
                for (int h = 0; h < 2; h++) {
                    int rl = am0 + mb * 16 + h * 8 + g;
                    float iz = __ldg(&g_invZ[mbase + rl]);
                    size_t rb = (size_t)(mbase + rl) * VOCABN + vb * 128;
                    if (full_tile) {
                        #pragma unroll
                        for (int nb = 0; nb < 8; nb++) {
                            int cl = bn0 + nb * 8 + t4 * 2;
                            float p0 = __expf(acc[mb][nb][h * 2]     + bb0[nb]) * iz;
                            float p1 = __expf(acc[mb][nb][h * 2 + 1] + bb1[nb]) * iz;
                            *reinterpret_cast<float2*>(out + rb + cl) = make_float2(p0, p1);
                        }
                    } else {
                        #pragma unroll
                        for (int nb = 0; nb < 8; nb++) {
                            int cl = bn0 + nb * 8 + t4 * 2;
                            if (vb * 128 + cl < VOCABN) {
                                float p0 = __expf(acc[mb][nb][h * 2]     + bb0[nb]) * iz;
                                float p1 = __expf(acc[mb][nb][h * 2 + 1] + bb1[nb]) * iz;
                                *reinterpret_cast<float2*>(out + rb + cl) = make_float2(p0, p1);
                            }
                        }
                    }
                }
            }
        }
        CP_WAIT0();
        __syncthreads();
    }
}

// ---------------------------------------------------------------------------
// Kernel C: per-row plain sum of NCHP partials -> invZ
// ---------------------------------------------------------------------------
__global__ void reduce_kernel() {
    const int row = blockIdx.x;
    const int t = threadIdx.x;    // 256
    float s = 0.f;
    const float* p = &g_psum[(size_t)row * NCHP];
    for (int i = t; i < NCHP; i += 256) s += p[i];
    __shared__ float ss[256];
    ss[t] = s;
    __syncthreads();
    for (int stride = 128; stride > 0; stride >>= 1) {
        if (t < stride) ss[t] += ss[t + stride];
        __syncthreads();
    }
    if (t == 0) g_invZ[row] = 1.f / ss[0];
}

// ---------------------------------------------------------------------------
extern "C" void kernel_launch(void* const* d_in, const int* in_sizes, int n_in,
                              void* d_out, int out_size) {
    const int*   x     = (const int*)d_in[0];
    const float* noise = (const float*)d_in[1];
    const float* emb   = (const float*)d_in[2];
    const float* W_ih  = (const float*)d_in[3];
    /* d_in[4] = W_hh — dead: h0 == 0 */
    const float* b_ih  = (const float*)d_in[5];
    const float* b_hh  = (const float*)d_in[6];
    const float* fc_w  = (const float*)d_in[7];
    const float* fc_b  = (const float*)d_in[8];
    float* out = (float*)d_out;

    const int smemA = (384 * WPAD + A_ROWS * CIN) * 4;
    cudaFuncSetAttribute(lstm_kernel, cudaFuncAttributeMaxDynamicSharedMemorySize, smemA);
    cudaFuncSetAttribute(gemm_tc<1>, cudaFuncAttributeMaxDynamicSharedMemorySize, SMEM_GEMM);
    cudaFuncSetAttribute(gemm_tc<2>, cudaFuncAttributeMaxDynamicSharedMemorySize, SMEM_GEMM);

    convert_w_kernel<<<(NCH * 2048) / 256, 256>>>(fc_w);
    lstm_kernel<<<BATCH / A_ROWS, 256, smemA>>>(x, noise, emb, W_ih, b_ih, b_hh);
    convert_a_kernel<<<(MT16 * 2048) / 256, 256>>>();
    gemm_tc<1><<<NCH, 256, SMEM_GEMM>>>(fc_b, out);
    reduce_kernel<<<BATCH, 256>>>();
    gemm_tc<2><<<NCH, 256, SMEM_GEMM>>>(fc_b, out);
}

// round 9
// speedup vs baseline: 4.3886x; 1.0149x over previous
#include <cuda_runtime.h>
#include <cuda_bf16.h>
#include <math.h>
#include <math_constants.h>
#include <cstdint>

// Problem constants
#define VOCABN 100000
#define EMBED  100
#define NOISEN 10
#define CIN    110
#define HID    128
#define BATCH  2048

// GEMM tiling
#define NCH 782                 // ceil(100000/128): vocab tiles of 128
#define NCHP (2 * NCH)          // partials per row (two wn halves per tile)
#define MT16 16                 // 128-row A tiles
#define TILE_BYTES 32768        // 128x128 bf16 tile

#define LOG2E 1.4426950408889634f

// LSTM kernel tiling
#define A_ROWS 16
#define WPAD   111

// ---------------------------------------------------------------------------
// Scratch (static __device__, no allocations)
// ---------------------------------------------------------------------------
__device__ __align__(16) char g_B[(size_t)NCH * TILE_BYTES];     // 25.6 MB bf16 tiles
__device__ __align__(16) char g_A[MT16 * TILE_BYTES];            // 512 KB (log2e-scaled)
__device__ float g_psum[(size_t)BATCH * NCHP];                   // 12.8 MB
__device__ float g_invZ[BATCH];

__device__ __forceinline__ float sigm(float v) { return 1.0f / (1.0f + expf(-v)); }

__device__ __forceinline__ uint32_t smem_to_u32(const void* p) {
    uint32_t a;
    asm("{ .reg .u64 t; cvta.to.shared.u64 t, %1; cvt.u32.u64 %0, t; }" : "=r"(a) : "l"(p));
    return a;
}

__device__ __forceinline__ float ex2f(float x) {
    float r;
    asm("ex2.approx.f32 %0, %1;" : "=f"(r) : "f"(x));
    return r;
}

// Blocked-atom SW128 byte offset inside a 128x128 bf16 tile (conflict-free ldsm)
__host__ __device__ __forceinline__ uint32_t tile_off(int row, int col) {
    return (uint32_t)((((row >> 3) + ((col >> 6) << 4)) << 10) +
                      ((row & 7) << 7) + ((((col & 63) << 1)) ^ ((row & 7) << 4)));
}

__device__ __forceinline__ void ldsm_x4(uint32_t* r, uint32_t addr) {
    asm volatile("ldmatrix.sync.aligned.m8n8.x4.shared.b16 {%0,%1,%2,%3}, [%4];"
                 : "=r"(r[0]), "=r"(r[1]), "=r"(r[2]), "=r"(r[3]) : "r"(addr));
}

__device__ __forceinline__ void mma16816(float* c, const uint32_t* a, uint32_t b0, uint32_t b1) {
    asm volatile(
        "mma.sync.aligned.m16n8k16.row.col.f32.bf16.bf16.f32 "
        "{%0,%1,%2,%3}, {%4,%5,%6,%7}, {%8,%9}, {%0,%1,%2,%3};"
        : "+f"(c[0]), "+f"(c[1]), "+f"(c[2]), "+f"(c[3])
        : "r"(a[0]), "r"(a[1]), "r"(a[2]), "r"(a[3]), "r"(b0), "r"(b1));
}

__device__ __forceinline__ void cp_async16(uint32_t saddr, const void* gaddr) {
    asm volatile("cp.async.cg.shared.global [%0], [%1], 16;" :: "r"(saddr), "l"(gaddr));
}
#define CP_COMMIT() asm volatile("cp.async.commit_group;" ::: "memory")
#define CP_WAIT0()  asm volatile("cp.async.wait_group 0;" ::: "memory")

// K-step address transform for the hoisted ldsm base
#define KADDR(base, ks) ((((ks) >= 4) ? ((base) + 16384u) : (base)) ^ (uint32_t)(((ks) & 3) << 5))

// ---------------------------------------------------------------------------
// Kernel A: embedding + noise + LSTM step -> swizzled bf16 A tiles directly
// (values pre-scaled by log2(e)).
// ---------------------------------------------------------------------------
__global__ void lstm_kernel(const int* __restrict__ x,
                            const float* __restrict__ noise,
                            const float* __restrict__ emb,
                            const float* __restrict__ W_ih,
                            const float* __restrict__ b_ih,
                            const float* __restrict__ b_hh) {
    extern __shared__ float sm[];
    float* Wsm = sm;                       // [384][WPAD]
    float* Csm = sm + 384 * WPAD;          // [A_ROWS][CIN]

    const int t = threadIdx.x;
    const int row0 = blockIdx.x * A_ROWS;

    for (int idx = t; idx < 384 * CIN; idx += 256) {
        int r = idx / CIN;
        int k = idx - r * CIN;
        int gr = (r < 128) ? r : (r + 128);   // skip dead f block
        Wsm[r * WPAD + k] = W_ih[gr * CIN + k];
    }
    for (int idx = t; idx < A_ROWS * CIN; idx += 256) {
        int r = idx / CIN;
        int k = idx - r * CIN;
        int brow = row0 + r;
        float v = (k < EMBED) ? emb[(size_t)x[brow] * EMBED + k]
                              : noise[brow * NOISEN + (k - EMBED)];
        Csm[r * CIN + k] = v;
    }
    __syncthreads();

    const int j = t & 127;
    const int rhalf = t >> 7;
    const float bi = b_ih[j]       + b_hh[j];
    const float bg = b_ih[256 + j] + b_hh[256 + j];
    const float bo = b_ih[384 + j] + b_hh[384 + j];

    const float* wi = &Wsm[j * WPAD];
    const float* wg = &Wsm[(128 + j) * WPAD];
    const float* wo = &Wsm[(256 + j) * WPAD];

    for (int rr = 0; rr < A_ROWS / 2; rr++) {
        int r = rhalf * (A_ROWS / 2) + rr;
        const float* c = &Csm[r * CIN];
        float ai = bi, ag = bg, ao = bo;
        #pragma unroll 2
        for (int k = 0; k < CIN; k++) {
            float cv = c[k];
            ai = fmaf(wi[k], cv, ai);
            ag = fmaf(wg[k], cv, ag);
            ao = fmaf(wo[k], cv, ao);
        }
        float cc = sigm(ai) * tanhf(ag);
        float h  = sigm(ao) * tanhf(cc);

        // Pre-scale by log2(e); pack adjacent cols and store swizzled bf16x2
        float hs = h * LOG2E;
        float hn = __shfl_xor_sync(0xffffffffu, hs, 1);
        if (!(t & 1)) {
            __nv_bfloat162 h2 = __floats2bfloat162_rn(hs, hn);
            int row = row0 + r;
            uint32_t off = (uint32_t)(row >> 7) * TILE_BYTES + tile_off(row & 127, j);
            *reinterpret_cast<uint32_t*>(g_A + off) = *reinterpret_cast<uint32_t*>(&h2);
        }
    }
}

// ---------------------------------------------------------------------------
// Convert fc_w -> swizzled bf16 tiles (pad rows beyond VOCAB with 0)
// ---------------------------------------------------------------------------
__global__ void convert_w_kernel(const float* __restrict__ fc_w) {
    int c = blockIdx.x * blockDim.x + threadIdx.x;     // 16B-chunk id
    int tile = c >> 11;
    int q = c & 2047;
    int row = q >> 4;
    int kc = q & 15;
    int v = tile * 128 + row;

    float4 w0, w1;
    if (v < VOCABN) {
        const float4* src = reinterpret_cast<const float4*>(fc_w + (size_t)v * HID + kc * 8);
        w0 = src[0]; w1 = src[1];
    } else {
        w0 = w1 = make_float4(0.f, 0.f, 0.f, 0.f);
    }
    float f[8] = {w0.x, w0.y, w0.z, w0.w, w1.x, w1.y, w1.z, w1.w};
    __nv_bfloat16 hv[8];
    #pragma unroll
    for (int i = 0; i < 8; i++) hv[i] = __float2bfloat16(f[i]);
    size_t off = (size_t)tile * TILE_BYTES + tile_off(row, kc * 8);
    *reinterpret_cast<uint4*>(g_B + off) = *reinterpret_cast<uint4*>(hv);
}

// ---------------------------------------------------------------------------
// Shared GEMM skeleton. Accumulator = log2e*(logit+bias) via pre-scaled A and
// bias-as-c-init. PHASE==1: sumexp partials (ex2). PHASE==2: probs direct.
// ---------------------------------------------------------------------------
#define OFF_B     0              // 32 KB
#define OFF_A     32768          // 2 x 32 KB
#define OFF_BIAS  98304          // 512 B
#define SMEM_GEMM 98816

template <int PHASE>
__global__ __launch_bounds__(256, 2) void gemm_tc(const float* __restrict__ fc_b,
                                                  float* __restrict__ out) {
    extern __shared__ char smem[];
    const int t = threadIdx.x, wid = t >> 5, lane = t & 31;
    const int vb = blockIdx.x;
    const uint32_t sb = smem_to_u32(smem);

    const int wm = wid >> 1;      // 0..3 : 32-row slab
    const int wn = wid & 1;       // 0..1 : 64-col slab
    const int g = lane >> 2, t4 = lane & 3;

    // Stage B tile + scaled bias; start A[0] prefetch
    {
        const uint4* gb = reinterpret_cast<const uint4*>(g_B + (size_t)vb * TILE_BYTES);
        uint4* sbp = reinterpret_cast<uint4*>(smem + OFF_B);
        #pragma unroll
        for (int i = 0; i < 8; i++) sbp[t + 256 * i] = gb[t + 256 * i];
    }
    #pragma unroll
    for (int i = 0; i < 8; i++)
        cp_async16(sb + OFF_A + t * 16 + i * 4096, g_A + t * 16 + i * 4096);
    CP_COMMIT();
    if (t < 128) {
        int gc = vb * 128 + t;
        reinterpret_cast<float*>(smem + OFF_BIAS)[t] =
            (gc < VOCABN) ? LOG2E * fc_b[gc] : -CUDART_INF_F;
    }
    CP_WAIT0();
    __syncthreads();

    const int am0 = wm * 32;
    const int bn0 = wn * 64;

    // Hoisted ldsm base addresses
    const int sub = lane >> 3, rr = lane & 7;
    const int lrow = ((sub & 1) << 3) + rr;
    const int colp = (sub >> 1) << 3;
    const uint32_t baseA0 = sb + OFF_A + tile_off(am0 + lrow, colp);
    const uint32_t baseB  = sb + OFF_B + tile_off(bn0 + lrow, colp);

    // Scaled bias in registers (also the MMA c-init)
    float bb0[8], bb1[8];
    {
        const float* bias = reinterpret_cast<const float*>(smem + OFF_BIAS);
        #pragma unroll
        for (int nb = 0; nb < 8; nb++) {
            bb0[nb] = bias[bn0 + nb * 8 + t4 * 2];
            bb1[nb] = bias[bn0 + nb * 8 + t4 * 2 + 1];
        }
    }

    const bool full_tile = (vb < NCH - 1);

    for (int mt = 0; mt < MT16; mt++) {
        if (mt + 1 < MT16) {
            uint32_t dst = sb + OFF_A + ((mt + 1) & 1) * TILE_BYTES;
            const char* src = g_A + (size_t)(mt + 1) * TILE_BYTES;
            #pragma unroll
            for (int i = 0; i < 8; i++)
                cp_async16(dst + t * 16 + i * 4096, src + t * 16 + i * 4096);
            CP_COMMIT();
        }
        const int mbase = mt * 128;
        const uint32_t baseA = baseA0 + (mt & 1) * TILE_BYTES;

        // Init accumulators with the scaled bias (c-input of first MMA)
        float acc[2][8][4];
        #pragma unroll
        for (int mb = 0; mb < 2; mb++)
            #pragma unroll
            for (int nb = 0; nb < 8; nb++) {
                acc[mb][nb][0] = bb0[nb];
                acc[mb][nb][1] = bb1[nb];
                acc[mb][nb][2] = bb0[nb];
                acc[mb][nb][3] = bb1[nb];
            }

        #pragma unroll
        for (int ks = 0; ks < 8; ks++) {
            uint32_t a[2][4], b[4][4];
            #pragma unroll
            for (int mb = 0; mb < 2; mb++)
                ldsm_x4(a[mb], KADDR(baseA + mb * 2048, ks));
            #pragma unroll
            for (int nbb = 0; nbb < 4; nbb++)
                ldsm_x4(b[nbb], KADDR(baseB + nbb * 2048, ks));
            #pragma unroll
            for (int mb = 0; mb < 2; mb++)
                #pragma unroll
                for (int nbb = 0; nbb < 4; nbb++) {
                    mma16816(acc[mb][2 * nbb],     a[mb], b[nbb][0], b[nbb][2]);
                    mma16816(acc[mb][2 * nbb + 1], a[mb], b[nbb][1], b[nbb][3]);
                }
        }

        if (PHASE == 1) {
            // ---- sumexp partial per (row, wn-half): pure ex2 + adds ----
            #pragma unroll
            for (int mb = 0; mb < 2; mb++) {
                #pragma unroll
                for (int h = 0; h < 2; h++) {
                    int rl = am0 + mb * 16 + h * 8 + g;
                    float s = 0.f;
                    #pragma unroll
                    for (int nb = 0; nb < 8; nb++)
                        s += ex2f(acc[mb][nb][h * 2]) + ex2f(acc[mb][nb][h * 2 + 1]);
                    s += __shfl_xor_sync(0xffffffffu, s, 1);
                    s += __shfl_xor_sync(0xffffffffu, s, 2);
                    if (t4 == 0)
                        g_psum[(size_t)(mbase + rl) * NCHP + vb * 2 + wn] = s;
                }
            }
        } else {
            // ---- probs: p = ex2(acc) * invZ, direct STG ----
            #pragma unroll
            for (int mb = 0; mb < 2; mb++) {
                #pragma unroll
                for (int h = 0; h < 2; h++) {
                    int rl = am0 + mb * 16 + h * 8 + g;
                    float iz = __ldg(&g_invZ[mbase + rl]);
                    size_t rb = (size_t)(mbase + rl) * VOCABN + vb * 128;
                    if (full_tile) {
                        #pragma unroll
                        for (int nb = 0; nb < 8; nb++) {
                            int cl = bn0 + nb * 8 + t4 * 2;
                            float p0 = ex2f(acc[mb][nb][h * 2])     * iz;
                            float p1 = ex2f(acc[mb][nb][h * 2 + 1]) * iz;
                            *reinterpret_cast<float2*>(out + rb + cl) = make_float2(p0, p1);
                        }
                    } else {
                        #pragma unroll
                        for (int nb = 0; nb < 8; nb++) {
                            int cl = bn0 + nb * 8 + t4 * 2;
                            if (vb * 128 + cl < VOCABN) {
                                float p0 = ex2f(acc[mb][nb][h * 2])     * iz;
                                float p1 = ex2f(acc[mb][nb][h * 2 + 1]) * iz;
                                *reinterpret_cast<float2*>(out + rb + cl) = make_float2(p0, p1);
                            }
                        }
                    }
                }
            }
        }
        CP_WAIT0();
        __syncthreads();
    }
}

// ---------------------------------------------------------------------------
// Kernel C: per-row plain sum of NCHP partials -> invZ
// ---------------------------------------------------------------------------
__global__ void reduce_kernel() {
    const int row = blockIdx.x;
    const int t = threadIdx.x;    // 256
    float s = 0.f;
    const float* p = &g_psum[(size_t)row * NCHP];
    for (int i = t; i < NCHP; i += 256) s += p[i];
    __shared__ float ss[256];
    ss[t] = s;
    __syncthreads();
    for (int stride = 128; stride > 0; stride >>= 1) {
        if (t < stride) ss[t] += ss[t + stride];
        __syncthreads();
    }
    if (t == 0) g_invZ[row] = 1.f / ss[0];
}

// ---------------------------------------------------------------------------
extern "C" void kernel_launch(void* const* d_in, const int* in_sizes, int n_in,
                              void* d_out, int out_size) {
    const int*   x     = (const int*)d_in[0];
    const float* noise = (const float*)d_in[1];
    const float* emb   = (const float*)d_in[2];
    const float* W_ih  = (const float*)d_in[3];
    /* d_in[4] = W_hh — dead: h0 == 0 */
    const float* b_ih  = (const float*)d_in[5];
    const float* b_hh  = (const float*)d_in[6];
    const float* fc_w  = (const float*)d_in[7];
    const float* fc_b  = (const float*)d_in[8];
    float* out = (float*)d_out;

    const int smemA = (384 * WPAD + A_ROWS * CIN) * 4;
    cudaFuncSetAttribute(lstm_kernel, cudaFuncAttributeMaxDynamicSharedMemorySize, smemA);
    cudaFuncSetAttribute(gemm_tc<1>, cudaFuncAttributeMaxDynamicSharedMemorySize, SMEM_GEMM);
    cudaFuncSetAttribute(gemm_tc<2>, cudaFuncAttributeMaxDynamicSharedMemorySize, SMEM_GEMM);

    convert_w_kernel<<<(NCH * 2048) / 256, 256>>>(fc_w);
    lstm_kernel<<<BATCH / A_ROWS, 256, smemA>>>(x, noise, emb, W_ih, b_ih, b_hh);
    gemm_tc<1><<<NCH, 256, SMEM_GEMM>>>(fc_b, out);
    reduce_kernel<<<BATCH, 256>>>();
    gemm_tc<2><<<NCH, 256, SMEM_GEMM>>>(fc_b, out);
}

// round 10
// speedup vs baseline: 4.7580x; 1.0842x over previous
#include <cuda_runtime.h>
#include <cuda_bf16.h>
#include <math.h>
#include <math_constants.h>
#include <cstdint>

// Problem constants
#define VOCABN 100000
#define EMBED  100
#define NOISEN 10
#define CIN    110
#define HID    128
#define BATCH  2048

// GEMM tiling
#define NCHW 782                // 128-wide B tiles in g_B
#define NCH2 1563               // ceil(100000/64): 64-wide CTA tiles
#define NCHP (2 * NCH2)         // partials per row (two 32-col halves per CTA)
#define MT16 16                 // 128-row A tiles
#define TILE_BYTES 32768        // 128x128 bf16 tile

#define LOG2E 1.4426950408889634f

// LSTM kernel tiling
#define A_ROWS 16
#define WPAD   111

// ---------------------------------------------------------------------------
// Scratch (static __device__, no allocations)
// ---------------------------------------------------------------------------
__device__ __align__(16) char g_B[(size_t)NCHW * TILE_BYTES];    // 25.6 MB bf16 tiles
__device__ __align__(16) char g_A[MT16 * TILE_BYTES];            // 512 KB (log2e-scaled)
__device__ float g_psum[(size_t)BATCH * NCHP];                   // 25.6 MB
__device__ float g_invZ[BATCH];

__device__ __forceinline__ float sigm(float v) { return 1.0f / (1.0f + expf(-v)); }

__device__ __forceinline__ uint32_t smem_to_u32(const void* p) {
    uint32_t a;
    asm("{ .reg .u64 t; cvta.to.shared.u64 t, %1; cvt.u32.u64 %0, t; }" : "=r"(a) : "l"(p));
    return a;
}

__device__ __forceinline__ float ex2f(float x) {
    float r;
    asm("ex2.approx.f32 %0, %1;" : "=f"(r) : "f"(x));
    return r;
}

// Blocked-atom SW128 byte offset inside a 128x128 bf16 tile (16 atom-rows x 2 atom-cols)
__host__ __device__ __forceinline__ uint32_t tile_off(int row, int col) {
    return (uint32_t)((((row >> 3) + ((col >> 6) << 4)) << 10) +
                      ((row & 7) << 7) + ((((col & 63) << 1)) ^ ((row & 7) << 4)));
}

// Same swizzle for a 64x128 half tile (8 atom-rows x 2 atom-cols)
__device__ __forceinline__ uint32_t tile_off64(int row, int col) {
    return (uint32_t)((((row >> 3) + ((col >> 6) << 3)) << 10) +
                      ((row & 7) << 7) + ((((col & 63) << 1)) ^ ((row & 7) << 4)));
}

__device__ __forceinline__ void ldsm_x4(uint32_t* r, uint32_t addr) {
    asm volatile("ldmatrix.sync.aligned.m8n8.x4.shared.b16 {%0,%1,%2,%3}, [%4];"
                 : "=r"(r[0]), "=r"(r[1]), "=r"(r[2]), "=r"(r[3]) : "r"(addr));
}

__device__ __forceinline__ void mma16816(float* c, const uint32_t* a, uint32_t b0, uint32_t b1) {
    asm volatile(
        "mma.sync.aligned.m16n8k16.row.col.f32.bf16.bf16.f32 "
        "{%0,%1,%2,%3}, {%4,%5,%6,%7}, {%8,%9}, {%0,%1,%2,%3};"
        : "+f"(c[0]), "+f"(c[1]), "+f"(c[2]), "+f"(c[3])
        : "r"(a[0]), "r"(a[1]), "r"(a[2]), "r"(a[3]), "r"(b0), "r"(b1));
}

__device__ __forceinline__ void cp_async16(uint32_t saddr, const void* gaddr) {
    asm volatile("cp.async.cg.shared.global [%0], [%1], 16;" :: "r"(saddr), "l"(gaddr));
}
#define CP_COMMIT() asm volatile("cp.async.commit_group;" ::: "memory")
#define CP_WAIT0()  asm volatile("cp.async.wait_group 0;" ::: "memory")

// K-step address transform for the hoisted A ldsm base (full 128x128 tile)
#define KADDR(base, ks) ((((ks) >= 4) ? ((base) + 16384u) : (base)) ^ (uint32_t)(((ks) & 3) << 5))

// ---------------------------------------------------------------------------
// Kernel A: embedding + noise + LSTM step -> swizzled bf16 A tiles directly
// (values pre-scaled by log2(e)).
// ---------------------------------------------------------------------------
__global__ void lstm_kernel(const int* __restrict__ x,
                            const float* __restrict__ noise,
                            const float* __restrict__ emb,
                            const float* __restrict__ W_ih,
                            const float* __restrict__ b_ih,
                            const float* __restrict__ b_hh) {
    extern __shared__ float sm[];
    float* Wsm = sm;                       // [384][WPAD]
    float* Csm = sm + 384 * WPAD;          // [A_ROWS][CIN]

    const int t = threadIdx.x;
    const int row0 = blockIdx.x * A_ROWS;

    for (int idx = t; idx < 384 * CIN; idx += 256) {
        int r = idx / CIN;
        int k = idx - r * CIN;
        int gr = (r < 128) ? r : (r + 128);   // skip dead f block
        Wsm[r * WPAD + k] = W_ih[gr * CIN + k];
    }
    for (int idx = t; idx < A_ROWS * CIN; idx += 256) {
        int r = idx / CIN;
        int k = idx - r * CIN;
        int brow = row0 + r;
        float v = (k < EMBED) ? emb[(size_t)x[brow] * EMBED + k]
                              : noise[brow * NOISEN + (k - EMBED)];
        Csm[r * CIN + k] = v;
    }
    __syncthreads();

    const int j = t & 127;
    const int rhalf = t >> 7;
    const float bi = b_ih[j]       + b_hh[j];
    const float bg = b_ih[256 + j] + b_hh[256 + j];
    const float bo = b_ih[384 + j] + b_hh[384 + j];

    const float* wi = &Wsm[j * WPAD];
    const float* wg = &Wsm[(128 + j) * WPAD];
    const float* wo = &Wsm[(256 + j) * WPAD];

    for (int rr = 0; rr < A_ROWS / 2; rr++) {
        int r = rhalf * (A_ROWS / 2) + rr;
        const float* c = &Csm[r * CIN];
        float ai = bi, ag = bg, ao = bo;
        #pragma unroll 2
        for (int k = 0; k < CIN; k++) {
            float cv = c[k];
            ai = fmaf(wi[k], cv, ai);
            ag = fmaf(wg[k], cv, ag);
            ao = fmaf(wo[k], cv, ao);
        }
        float cc = sigm(ai) * tanhf(ag);
        float h  = sigm(ao) * tanhf(cc);

        // Pre-scale by log2(e); pack adjacent cols and store swizzled bf16x2
        float hs = h * LOG2E;
        float hn = __shfl_xor_sync(0xffffffffu, hs, 1);
        if (!(t & 1)) {
            __nv_bfloat162 h2 = __floats2bfloat162_rn(hs, hn);
            int row = row0 + r;
            uint32_t off = (uint32_t)(row >> 7) * TILE_BYTES + tile_off(row & 127, j);
            *reinterpret_cast<uint32_t*>(g_A + off) = *reinterpret_cast<uint32_t*>(&h2);
        }
    }
}

// ---------------------------------------------------------------------------
// Convert fc_w -> swizzled bf16 tiles (pad rows beyond VOCAB with 0)
// ---------------------------------------------------------------------------
__global__ void convert_w_kernel(const float* __restrict__ fc_w) {
    int c = blockIdx.x * blockDim.x + threadIdx.x;     // 16B-chunk id
    int tile = c >> 11;
    int q = c & 2047;
    int row = q >> 4;
    int kc = q & 15;
    int v = tile * 128 + row;

    float4 w0, w1;
    if (v < VOCABN) {
        const float4* src = reinterpret_cast<const float4*>(fc_w + (size_t)v * HID + kc * 8);
        w0 = src[0]; w1 = src[1];
    } else {
        w0 = w1 = make_float4(0.f, 0.f, 0.f, 0.f);
    }
    float f[8] = {w0.x, w0.y, w0.z, w0.w, w1.x, w1.y, w1.z, w1.w};
    __nv_bfloat16 hv[8];
    #pragma unroll
    for (int i = 0; i < 8; i++) hv[i] = __float2bfloat16(f[i]);
    size_t off = (size_t)tile * TILE_BYTES + tile_off(row, kc * 8);
    *reinterpret_cast<uint4*>(g_B + off) = *reinterpret_cast<uint4*>(hv);
}

// ---------------------------------------------------------------------------
// GEMM: CTA owns a 64-col vocab slab; B operand held entirely in registers.
// Warps 4(M)x2(N), warp tile 32x32. A double-buffered via cp.async.
// PHASE==1: sumexp partials. PHASE==2: probs direct.
// ---------------------------------------------------------------------------
#define OFF_BS    0              // 16 KB staged half B tile
#define OFF_A     16384          // 2 x 32 KB
#define OFF_BIAS  81920          // 64 floats
#define SMEM_GEMM 82176

template <int PHASE>
__global__ __launch_bounds__(256, 2) void gemm_tc(const float* __restrict__ fc_b,
                                                  float* __restrict__ out) {
    extern __shared__ char smem[];
    const int t = threadIdx.x, wid = t >> 5, lane = t & 31;
    const int vb = blockIdx.x;          // 64-col slab id
    const uint32_t sb = smem_to_u32(smem);

    const int wm = wid >> 1;      // 0..3 : 32-row slab
    const int wn = wid & 1;       // 0..1 : 32-col slab
    const int g = lane >> 2, t4 = lane & 3;

    // Stage the 64-row half of B tile (16 atoms of 1024B)
    {
        const char* gtile = g_B + (size_t)(vb >> 1) * TILE_BYTES;
        const int half = vb & 1;
        #pragma unroll
        for (int i = 0; i < 4; i++) {
            int chunk = t + 256 * i;          // 16B chunk id, 1024 total
            int datom = chunk >> 6;           // 0..15
            int within = chunk & 63;
            int ar = datom & 7, ac = datom >> 3;
            int satom = 8 * half + ar + ac * 16;
            *reinterpret_cast<uint4*>(smem + OFF_BS + datom * 1024 + within * 16) =
                *reinterpret_cast<const uint4*>(gtile + (size_t)satom * 1024 + within * 16);
        }
    }
    // A[0] prefetch + bias staging
    #pragma unroll
    for (int i = 0; i < 8; i++)
        cp_async16(sb + OFF_A + t * 16 + i * 4096, g_A + t * 16 + i * 4096);
    CP_COMMIT();
    if (t < 64) {
        int gc = vb * 64 + t;
        reinterpret_cast<float*>(smem + OFF_BIAS)[t] =
            (gc < VOCABN) ? LOG2E * fc_b[gc] : -CUDART_INF_F;
    }
    __syncthreads();

    // Lane mapping for ldsm
    const int sub = lane >> 3, rr = lane & 7;
    const int lrow = ((sub & 1) << 3) + rr;
    const int colp = (sub >> 1) << 3;

    // Load this warp's B operand into registers: 8 ks x 2 n16-blocks x 4 regs
    uint32_t bf[8][2][4];
    {
        const int brow0 = wn * 32;
        #pragma unroll
        for (int ks = 0; ks < 8; ks++)
            #pragma unroll
            for (int nbb = 0; nbb < 2; nbb++)
                ldsm_x4(bf[ks][nbb],
                        sb + OFF_BS + tile_off64(brow0 + nbb * 16 + lrow, ks * 16 + colp));
    }

    const int am0 = wm * 32;
    const uint32_t baseA0 = sb + OFF_A + tile_off(am0 + lrow, colp);
    const float* bias = reinterpret_cast<const float*>(smem + OFF_BIAS);
    CP_WAIT0();
    __syncthreads();

    const bool full_tile = (vb < NCH2 - 1);

    for (int mt = 0; mt < MT16; mt++) {
        if (mt + 1 < MT16) {
            uint32_t dst = sb + OFF_A + ((mt + 1) & 1) * TILE_BYTES;
            const char* src = g_A + (size_t)(mt + 1) * TILE_BYTES;
            #pragma unroll
            for (int i = 0; i < 8; i++)
                cp_async16(dst + t * 16 + i * 4096, src + t * 16 + i * 4096);
            CP_COMMIT();
        }
        const int mbase = mt * 128;
        const uint32_t baseA = baseA0 + (mt & 1) * TILE_BYTES;

        // acc init from scaled bias (re-read from smem each tile; saves regs)
        float acc[2][4][4];
        #pragma unroll
        for (int nb = 0; nb < 4; nb++) {
            float2 bv = *reinterpret_cast<const float2*>(bias + wn * 32 + nb * 8 + t4 * 2);
            #pragma unroll
            for (int mb = 0; mb < 2; mb++) {
                acc[mb][nb][0] = bv.x;
                acc[mb][nb][1] = bv.y;
                acc[mb][nb][2] = bv.x;
                acc[mb][nb][3] = bv.y;
            }
        }

        #pragma unroll
        for (int ks = 0; ks < 8; ks++) {
            uint32_t a[2][4];
            #pragma unroll
            for (int mb = 0; mb < 2; mb++)
                ldsm_x4(a[mb], KADDR(baseA + mb * 2048, ks));
            #pragma unroll
            for (int mb = 0; mb < 2; mb++)
                #pragma unroll
                for (int nbb = 0; nbb < 2; nbb++) {
                    mma16816(acc[mb][2 * nbb],     a[mb], bf[ks][nbb][0], bf[ks][nbb][2]);
                    mma16816(acc[mb][2 * nbb + 1], a[mb], bf[ks][nbb][1], bf[ks][nbb][3]);
                }
        }

        if (PHASE == 1) {
            // ---- sumexp partial per (row, 32-col half) ----
            #pragma unroll
            for (int mb = 0; mb < 2; mb++) {
                #pragma unroll
                for (int h = 0; h < 2; h++) {
                    int rl = am0 + mb * 16 + h * 8 + g;
                    float s = 0.f;
                    #pragma unroll
                    for (int nb = 0; nb < 4; nb++)
                        s += ex2f(acc[mb][nb][h * 2]) + ex2f(acc[mb][nb][h * 2 + 1]);
                    s += __shfl_xor_sync(0xffffffffu, s, 1);
                    s += __shfl_xor_sync(0xffffffffu, s, 2);
                    if (t4 == 0)
                        g_psum[(size_t)(mbase + rl) * NCHP + vb * 2 + wn] = s;
                }
            }
        } else {
            // ---- probs: p = ex2(acc) * invZ, direct STG ----
            #pragma unroll
            for (int mb = 0; mb < 2; mb++) {
                #pragma unroll
                for (int h = 0; h < 2; h++) {
                    int rl = am0 + mb * 16 + h * 8 + g;
                    float iz = __ldg(&g_invZ[mbase + rl]);
                    size_t rb = (size_t)(mbase + rl) * VOCABN + vb * 64;
                    if (full_tile) {
                        #pragma unroll
                        for (int nb = 0; nb < 4; nb++) {
                            int cl = wn * 32 + nb * 8 + t4 * 2;
                            float p0 = ex2f(acc[mb][nb][h * 2])     * iz;
                            float p1 = ex2f(acc[mb][nb][h * 2 + 1]) * iz;
                            *reinterpret_cast<float2*>(out + rb + cl) = make_float2(p0, p1);
                        }
                    } else {
                        #pragma unroll
                        for (int nb = 0; nb < 4; nb++) {
                            int cl = wn * 32 + nb * 8 + t4 * 2;
                            if (vb * 64 + cl < VOCABN) {
                                float p0 = ex2f(acc[mb][nb][h * 2])     * iz;
                                float p1 = ex2f(acc[mb][nb][h * 2 + 1]) * iz;
                                *reinterpret_cast<float2*>(out + rb + cl) = make_float2(p0, p1);
                            }
                        }
                    }
                }
            }
        }
        CP_WAIT0();
        __syncthreads();
    }
}

// ---------------------------------------------------------------------------
// Kernel C: per-row plain sum of NCHP partials -> invZ
// ---------------------------------------------------------------------------
__global__ void reduce_kernel() {
    const int row = blockIdx.x;
    const int t = threadIdx.x;    // 256
    float s = 0.f;
    const float* p = &g_psum[(size_t)row * NCHP];
    for (int i = t; i < NCHP; i += 256) s += p[i];
    __shared__ float ss[256];
    ss[t] = s;
    __syncthreads();
    for (int stride = 128; stride > 0; stride >>= 1) {
        if (t < stride) ss[t] += ss[t + stride];
        __syncthreads();
    }
    if (t == 0) g_invZ[row] = 1.f / ss[0];
}

// ---------------------------------------------------------------------------
extern "C" void kernel_launch(void* const* d_in, const int* in_sizes, int n_in,
                              void* d_out, int out_size) {
    const int*   x     = (const int*)d_in[0];
    const float* noise = (const float*)d_in[1];
    const float* emb   = (const float*)d_in[2];
    const float* W_ih  = (const float*)d_in[3];
    /* d_in[4] = W_hh — dead: h0 == 0 */
    const float* b_ih  = (const float*)d_in[5];
    const float* b_hh  = (const float*)d_in[6];
    const float* fc_w  = (const float*)d_in[7];
    const float* fc_b  = (const float*)d_in[8];
    float* out = (float*)d_out;

    const int smemA = (384 * WPAD + A_ROWS * CIN) * 4;
    cudaFuncSetAttribute(lstm_kernel, cudaFuncAttributeMaxDynamicSharedMemorySize, smemA);
    cudaFuncSetAttribute(gemm_tc<1>, cudaFuncAttributeMaxDynamicSharedMemorySize, SMEM_GEMM);
    cudaFuncSetAttribute(gemm_tc<2>, cudaFuncAttributeMaxDynamicSharedMemorySize, SMEM_GEMM);

    convert_w_kernel<<<(NCHW * 2048) / 256, 256>>>(fc_w);
    lstm_kernel<<<BATCH / A_ROWS, 256, smemA>>>(x, noise, emb, W_ih, b_ih, b_hh);
    gemm_tc<1><<<NCH2, 256, SMEM_GEMM>>>(fc_b, out);
    reduce_kernel<<<BATCH, 256>>>();
    gemm_tc<2><<<NCH2, 256, SMEM_GEMM>>>(fc_b, out);
}

// round 12
// speedup vs baseline: 5.0779x; 1.0672x over previous
#include <cuda_runtime.h>
#include <cuda_bf16.h>
#include <math.h>
#include <math_constants.h>
#include <cstdint>

// Problem constants
#define VOCABN 100000
#define EMBED  100
#define NOISEN 10
#define CIN    110
#define HID    128
#define BATCH  2048

// GEMM tiling
#define NCH2 1563               // ceil(100000/64): 64-wide CTA slabs
#define NCHP (2 * NCH2)         // partials per row (two 32-col halves per CTA)
#define MT16 16                 // 128-row A tiles
#define TILE_BYTES 32768        // 128x128 bf16 tile

#define LOG2E 1.4426950408889634f

// LSTM kernel tiling
#define A_ROWS 16
#define WPAD   111

// ---------------------------------------------------------------------------
// Scratch (static __device__, no allocations)
// ---------------------------------------------------------------------------
__device__ __align__(16) char g_A[MT16 * TILE_BYTES];            // 512 KB (log2e-scaled)
__device__ float g_psum[(size_t)BATCH * NCHP];                   // 25.6 MB
__device__ float g_invZ[BATCH];

__device__ __forceinline__ float sigm(float v) { return 1.0f / (1.0f + expf(-v)); }

__device__ __forceinline__ uint32_t smem_to_u32(const void* p) {
    uint32_t a;
    asm("{ .reg .u64 t; cvta.to.shared.u64 t, %1; cvt.u32.u64 %0, t; }" : "=r"(a) : "l"(p));
    return a;
}

__device__ __forceinline__ float ex2f(float x) {
    float r;
    asm("ex2.approx.f32 %0, %1;" : "=f"(r) : "f"(x));
    return r;
}

// Blocked-atom SW128 byte offset inside a 128x128 bf16 tile (16 atom-rows x 2 atom-cols)
__host__ __device__ __forceinline__ uint32_t tile_off(int row, int col) {
    return (uint32_t)((((row >> 3) + ((col >> 6) << 4)) << 10) +
                      ((row & 7) << 7) + ((((col & 63) << 1)) ^ ((row & 7) << 4)));
}

// Same swizzle for a 64x128 tile (8 atom-rows x 2 atom-cols)
__device__ __forceinline__ uint32_t tile_off64(int row, int col) {
    return (uint32_t)((((row >> 3) + ((col >> 6) << 3)) << 10) +
                      ((row & 7) << 7) + ((((col & 63) << 1)) ^ ((row & 7) << 4)));
}

__device__ __forceinline__ void ldsm_x4(uint32_t* r, uint32_t addr) {
    asm volatile("ldmatrix.sync.aligned.m8n8.x4.shared.b16 {%0,%1,%2,%3}, [%4];"
                 : "=r"(r[0]), "=r"(r[1]), "=r"(r[2]), "=r"(r[3]) : "r"(addr));
}

__device__ __forceinline__ void mma16816(float* c, const uint32_t* a, uint32_t b0, uint32_t b1) {
    asm volatile(
        "mma.sync.aligned.m16n8k16.row.col.f32.bf16.bf16.f32 "
        "{%0,%1,%2,%3}, {%4,%5,%6,%7}, {%8,%9}, {%0,%1,%2,%3};"
        : "+f"(c[0]), "+f"(c[1]), "+f"(c[2]), "+f"(c[3])
        : "r"(a[0]), "r"(a[1]), "r"(a[2]), "r"(a[3]), "r"(b0), "r"(b1));
}

__device__ __forceinline__ void cp_async16(uint32_t saddr, const void* gaddr) {
    asm volatile("cp.async.cg.shared.global [%0], [%1], 16;" :: "r"(saddr), "l"(gaddr));
}
#define CP_COMMIT() asm volatile("cp.async.commit_group;" ::: "memory")
#define CP_WAIT0()  asm volatile("cp.async.wait_group 0;" ::: "memory")

// K-step address transform for the hoisted A ldsm base (full 128x128 tile)
#define KADDR(base, ks) ((((ks) >= 4) ? ((base) + 16384u) : (base)) ^ (uint32_t)(((ks) & 3) << 5))

// ---------------------------------------------------------------------------
// Kernel A: embedding + noise + LSTM step -> swizzled bf16 A tiles directly
// (values pre-scaled by log2(e)).
// ---------------------------------------------------------------------------
__global__ void lstm_kernel(const int* __restrict__ x,
                            const float* __restrict__ noise,
                            const float* __restrict__ emb,
                            const float* __restrict__ W_ih,
                            const float* __restrict__ b_ih,
                            const float* __restrict__ b_hh) {
    extern __shared__ float sm[];
    float* Wsm = sm;                       // [384][WPAD]
    float* Csm = sm + 384 * WPAD;          // [A_ROWS][CIN]

    const int t = threadIdx.x;
    const int row0 = blockIdx.x * A_ROWS;

    for (int idx = t; idx < 384 * CIN; idx += 256) {
        int r = idx / CIN;
        int k = idx - r * CIN;
        int gr = (r < 128) ? r : (r + 128);   // skip dead f block
        Wsm[r * WPAD + k] = W_ih[gr * CIN + k];
    }
    for (int idx = t; idx < A_ROWS * CIN; idx += 256) {
        int r = idx / CIN;
        int k = idx - r * CIN;
        int brow = row0 + r;
        float v = (k < EMBED) ? emb[(size_t)x[brow] * EMBED + k]
                              : noise[brow * NOISEN + (k - EMBED)];
        Csm[r * CIN + k] = v;
    }
    __syncthreads();

    const int j = t & 127;
    const int rhalf = t >> 7;
    const float bi = b_ih[j]       + b_hh[j];
    const float bg = b_ih[256 + j] + b_hh[256 + j];
    const float bo = b_ih[384 + j] + b_hh[384 + j];

    const float* wi = &Wsm[j * WPAD];
    const float* wg = &Wsm[(128 + j) * WPAD];
    const float* wo = &Wsm[(256 + j) * WPAD];

    for (int rr = 0; rr < A_ROWS / 2; rr++) {
        int r = rhalf * (A_ROWS / 2) + rr;
        const float* c = &Csm[r * CIN];
        float ai = bi, ag = bg, ao = bo;
        #pragma unroll 2
        for (int k = 0; k < CIN; k++) {
            float cv = c[k];
            ai = fmaf(wi[k], cv, ai);
            ag = fmaf(wg[k], cv, ag);
            ao = fmaf(wo[k], cv, ao);
        }
        float cc = sigm(ai) * tanhf(ag);
        float h  = sigm(ao) * tanhf(cc);

        // Pre-scale by log2(e); pack adjacent cols and store swizzled bf16x2
        float hs = h * LOG2E;
        float hn = __shfl_xor_sync(0xffffffffu, hs, 1);
        if (!(t & 1)) {
            __nv_bfloat162 h2 = __floats2bfloat162_rn(hs, hn);
            int row = row0 + r;
            uint32_t off = (uint32_t)(row >> 7) * TILE_BYTES + tile_off(row & 127, j);
            *reinterpret_cast<uint32_t*>(g_A + off) = *reinterpret_cast<uint32_t*>(&h2);
        }
    }
}

// ---------------------------------------------------------------------------
// GEMM: CTA owns a 64-col vocab slab; B staged from fc_w (fp32->bf16 inline),
// then held entirely in registers. Warps 4(M)x2(N), warp tile 32x32.
// A double-buffered via cp.async. PHASE==1: sumexp partials. PHASE==2: probs.
// ---------------------------------------------------------------------------
#define OFF_BS    0              // 16 KB staged B slab (64 rows x 128 cols bf16)
#define OFF_A     16384          // 2 x 32 KB
#define OFF_BIAS  81920          // 64 floats
#define SMEM_GEMM 82176

template <int PHASE>
__global__ __launch_bounds__(256, 2) void gemm_tc(const float* __restrict__ fc_w,
                                                  const float* __restrict__ fc_b,
                                                  float* __restrict__ out) {
    extern __shared__ char smem[];
    const int t = threadIdx.x, wid = t >> 5, lane = t & 31;
    const int vb = blockIdx.x;          // 64-col slab id
    const uint32_t sb = smem_to_u32(smem);

    const int wm = wid >> 1;      // 0..3 : 32-row slab
    const int wn = wid & 1;       // 0..1 : 32-col slab
    const int g = lane >> 2, t4 = lane & 3;

    // A[0] prefetch first (longest latency)
    #pragma unroll
    for (int i = 0; i < 8; i++)
        cp_async16(sb + OFF_A + t * 16 + i * 4096, g_A + t * 16 + i * 4096);
    CP_COMMIT();

    // Stage B slab: fc_w rows vb*64..+63, fp32 -> bf16, swizzled 64x128 tile.
    // 4 threads per row, each thread 4 chunks of 8 cols.
    {
        const int row = t >> 2;
        const int v = vb * 64 + row;
        const bool valid = (v < VOCABN);
        const float4* src = reinterpret_cast<const float4*>(fc_w + (size_t)v * HID);
        #pragma unroll
        for (int i = 0; i < 4; i++) {
            int c8 = (t & 3) + 4 * i;      // 8-col chunk 0..15
            float4 w0, w1;
            if (valid) { w0 = src[c8 * 2]; w1 = src[c8 * 2 + 1]; }
            else       { w0 = w1 = make_float4(0.f, 0.f, 0.f, 0.f); }
            __nv_bfloat162 p0 = __floats2bfloat162_rn(w0.x, w0.y);
            __nv_bfloat162 p1 = __floats2bfloat162_rn(w0.z, w0.w);
            __nv_bfloat162 p2 = __floats2bfloat162_rn(w1.x, w1.y);
            __nv_bfloat162 p3 = __floats2bfloat162_rn(w1.z, w1.w);
            uint4 packed = make_uint4(*reinterpret_cast<uint32_t*>(&p0),
                                      *reinterpret_cast<uint32_t*>(&p1),
                                      *reinterpret_cast<uint32_t*>(&p2),
                                      *reinterpret_cast<uint32_t*>(&p3));
            *reinterpret_cast<uint4*>(smem + OFF_BS + tile_off64(row, c8 * 8)) = packed;
        }
    }
    if (t < 64) {
        int gc = vb * 64 + t;
        reinterpret_cast<float*>(smem + OFF_BIAS)[t] =
            (gc < VOCABN) ? LOG2E * fc_b[gc] : -CUDART_INF_F;
    }
    __syncthreads();

    // Lane mapping for ldsm
    const int sub = lane >> 3, rr = lane & 7;
    const int lrow = ((sub & 1) << 3) + rr;
    const int colp = (sub >> 1) << 3;

    // Load this warp's B operand into registers: 8 ks x 2 n16-blocks x 4 regs
    uint32_t bf[8][2][4];
    {
        const int brow0 = wn * 32;
        #pragma unroll
        for (int ks = 0; ks < 8; ks++)
            #pragma unroll
            for (int nbb = 0; nbb < 2; nbb++)
                ldsm_x4(bf[ks][nbb],
                        sb + OFF_BS + tile_off64(brow0 + nbb * 16 + lrow, ks * 16 + colp));
    }

    const int am0 = wm * 32;
    const uint32_t baseA0 = sb + OFF_A + tile_off(am0 + lrow, colp);
    const float* bias = reinterpret_cast<const float*>(smem + OFF_BIAS);
    CP_WAIT0();
    __syncthreads();

    const bool full_tile = (vb < NCH2 - 1);

    for (int mt = 0; mt < MT16; mt++) {
        if (mt + 1 < MT16) {
            uint32_t dst = sb + OFF_A + ((mt + 1) & 1) * TILE_BYTES;
            const char* src = g_A + (size_t)(mt + 1) * TILE_BYTES;
            #pragma unroll
            for (int i = 0; i < 8; i++)
                cp_async16(dst + t * 16 + i * 4096, src + t * 16 + i * 4096);
            CP_COMMIT();
        }
        const int mbase = mt * 128;
        const uint32_t baseA = baseA0 + (mt & 1) * TILE_BYTES;

        // acc init from scaled bias (re-read from smem each tile; saves regs)
        float acc[2][4][4];
        #pragma unroll
        for (int nb = 0; nb < 4; nb++) {
            float2 bv = *reinterpret_cast<const float2*>(bias + wn * 32 + nb * 8 + t4 * 2);
            #pragma unroll
            for (int mb = 0; mb < 2; mb++) {
                acc[mb][nb][0] = bv.x;
                acc[mb][nb][1] = bv.y;
                acc[mb][nb][2] = bv.x;
                acc[mb][nb][3] = bv.y;
            }
        }

        #pragma unroll
        for (int ks = 0; ks < 8; ks++) {
            uint32_t a[2][4];
            #pragma unroll
            for (int mb = 0; mb < 2; mb++)
                ldsm_x4(a[mb], KADDR(baseA + mb * 2048, ks));
            #pragma unroll
            for (int mb = 0; mb < 2; mb++)
                #pragma unroll
                for (int nbb = 0; nbb < 2; nbb++) {
                    mma16816(acc[mb][2 * nbb],     a[mb], bf[ks][nbb][0], bf[ks][nbb][2]);
                    mma16816(acc[mb][2 * nbb + 1], a[mb], bf[ks][nbb][1], bf[ks][nbb][3]);
                }
        }

        if (PHASE == 1) {
            // ---- sumexp partial per (row, 32-col half) ----
            #pragma unroll
            for (int mb = 0; mb < 2; mb++) {
                #pragma unroll
                for (int h = 0; h < 2; h++) {
                    int rl = am0 + mb * 16 + h * 8 + g;
                    float s = 0.f;
                    #pragma unroll
                    for (int nb = 0; nb < 4; nb++)
                        s += ex2f(acc[mb][nb][h * 2]) + ex2f(acc[mb][nb][h * 2 + 1]);
                    s += __shfl_xor_sync(0xffffffffu, s, 1);
                    s += __shfl_xor_sync(0xffffffffu, s, 2);
                    if (t4 == 0)
                        g_psum[(size_t)(mbase + rl) * NCHP + vb * 2 + wn] = s;
                }
            }
        } else {
            // ---- probs: p = ex2(acc) * invZ, direct STG ----
            // Hoist the 4 invZ loads so their L2 latency overlaps the exp chain
            float iz[2][2];
            #pragma unroll
            for (int mb = 0; mb < 2; mb++)
                #pragma unroll
                for (int h = 0; h < 2; h++)
                    iz[mb][h] = __ldg(&g_invZ[mbase + am0 + mb * 16 + h * 8 + g]);

            #pragma unroll
            for (int mb = 0; mb < 2; mb++) {
                #pragma unroll
                for (int h = 0; h < 2; h++) {
                    int rl = am0 + mb * 16 + h * 8 + g;
                    size_t rb = (size_t)(mbase + rl) * VOCABN + vb * 64;
                    if (full_tile) {
                        #pragma unroll
                        for (int nb = 0; nb < 4; nb++) {
                            int cl = wn * 32 + nb * 8 + t4 * 2;
                            float p0 = ex2f(acc[mb][nb][h * 2])     * iz[mb][h];
                            float p1 = ex2f(acc[mb][nb][h * 2 + 1]) * iz[mb][h];
                            *reinterpret_cast<float2*>(out + rb + cl) = make_float2(p0, p1);
                        }
                    } else {
                        #pragma unroll
                        for (int nb = 0; nb < 4; nb++) {
                            int cl = wn * 32 + nb * 8 + t4 * 2;
                            if (vb * 64 + cl < VOCABN) {
                                float p0 = ex2f(acc[mb][nb][h * 2])     * iz[mb][h];
                                float p1 = ex2f(acc[mb][nb][h * 2 + 1]) * iz[mb][h];
                                *reinterpret_cast<float2*>(out + rb + cl) = make_float2(p0, p1);
                            }
                        }
                    }
                }
            }
        }
        CP_WAIT0();
        __syncthreads();
    }
}

// ---------------------------------------------------------------------------
// Kernel C: per-row plain sum of NCHP partials -> invZ
// ---------------------------------------------------------------------------
__global__ void reduce_kernel() {
    const int row = blockIdx.x;
    const int t = threadIdx.x;    // 256
    float s = 0.f;
    const float* p = &g_psum[(size_t)row * NCHP];
    for (int i = t; i < NCHP; i += 256) s += p[i];
    __shared__ float ss[256];
    ss[t] = s;
    __syncthreads();
    for (int stride = 128; stride > 0; stride >>= 1) {
        if (t < stride) ss[t] += ss[t + stride];
        __syncthreads();
    }
    if (t == 0) g_invZ[row] = 1.f / ss[0];
}

// ---------------------------------------------------------------------------
extern "C" void kernel_launch(void* const* d_in, const int* in_sizes, int n_in,
                              void* d_out, int out_size) {
    const int*   x     = (const int*)d_in[0];
    const float* noise = (const float*)d_in[1];
    const float* emb   = (const float*)d_in[2];
    const float* W_ih  = (const float*)d_in[3];
    /* d_in[4] = W_hh — dead: h0 == 0 */
    const float* b_ih  = (const float*)d_in[5];
    const float* b_hh  = (const float*)d_in[6];
    const float* fc_w  = (const float*)d_in[7];
    const float* fc_b  = (const float*)d_in[8];
    float* out = (float*)d_out;

    const int smemA = (384 * WPAD + A_ROWS * CIN) * 4;
    cudaFuncSetAttribute(lstm_kernel, cudaFuncAttributeMaxDynamicSharedMemorySize, smemA);
    cudaFuncSetAttribute(gemm_tc<1>, cudaFuncAttributeMaxDynamicSharedMemorySize, SMEM_GEMM);
    cudaFuncSetAttribute(gemm_tc<2>, cudaFuncAttributeMaxDynamicSharedMemorySize, SMEM_GEMM);

    lstm_kernel<<<BATCH / A_ROWS, 256, smemA>>>(x, noise, emb, W_ih, b_ih, b_hh);
    gemm_tc<1><<<NCH2, 256, SMEM_GEMM>>>(fc_w, fc_b, out);
    reduce_kernel<<<BATCH, 256>>>();
    gemm_tc<2><<<NCH2, 256, SMEM_GEMM>>>(fc_w, fc_b, out);
}